// round 9
// baseline (speedup 1.0000x reference)
#include <cuda_runtime.h>
#include <cuda_bf16.h>
#include <cstdint>

#define N       8192
#define D       128
#define BM      128
#define BN      128
#define NB      64
#define P       16
#define MARGINF 1.0f
#define EPSF    1e-12f
#define FINF    __int_as_float(0x7f800000)
#define INFBITS 0x7f800000

// smem layout (dynamic, 192KB): A hi | A lo | B buf0 (hi|lo) | B buf1 (hi|lo)
#define SMA_HI  0u
#define SMA_LO  32768u
#define SMB0    65536u
#define SMB_SZ  65536u

// Scratch (no allocation allowed -> device globals)
__device__ float g_sq[N];
__device__ int   g_maxp[N];     // float bits, order-independent atomics
__device__ int   g_minn[N];
__device__ float g_dc[N];       // min distance to normalized centers
__device__ __nv_bfloat16 g_xhi[N * D];
__device__ __nv_bfloat16 g_xlo[N * D];

// ---------------------------------------------------------------------------
static __device__ __forceinline__ uint32_t smem_u32(const void* p) {
    uint32_t a;
    asm("{ .reg .u64 t; cvta.to.shared.u64 t, %1; cvt.u32.u64 %0, t; }" : "=r"(a) : "l"(p));
    return a;
}
static __device__ __forceinline__ void ldsm4(uint32_t* r, uint32_t addr) {
    asm volatile("ldmatrix.sync.aligned.m8n8.x4.shared.b16 {%0,%1,%2,%3}, [%4];"
                 : "=r"(r[0]), "=r"(r[1]), "=r"(r[2]), "=r"(r[3]) : "r"(addr));
}
static __device__ __forceinline__ void mma16816(float* c, const uint32_t* a,
                                                const uint32_t* b) {
    asm volatile("mma.sync.aligned.m16n8k16.row.col.f32.bf16.bf16.f32 "
                 "{%0,%1,%2,%3}, {%4,%5,%6,%7}, {%8,%9}, {%0,%1,%2,%3};"
                 : "+f"(c[0]), "+f"(c[1]), "+f"(c[2]), "+f"(c[3])
                 : "r"(a[0]), "r"(a[1]), "r"(a[2]), "r"(a[3]), "r"(b[0]), "r"(b[1]));
}
static __device__ __forceinline__ void cpa16(uint32_t dst, const void* src) {
    asm volatile("cp.async.cg.shared.global [%0], [%1], 16;" :: "r"(dst), "l"(src) : "memory");
}
#define CPA_COMMIT() asm volatile("cp.async.commit_group;" ::: "memory")
#define CPA_WAIT(n)  asm volatile("cp.async.wait_group %0;" :: "n"(n) : "memory")

// 128x128 bf16 tile -> smem, 256B rows, 16B-chunk xor swizzle (256 threads).
static __device__ __forceinline__ void cpa_tile(uint32_t dst_s,
                                                const __nv_bfloat16* src,
                                                int row0, int tid) {
    const char* base = (const char*)(src + (size_t)row0 * D);
    #pragma unroll
    for (int i = 0; i < 8; i++) {
        int idx = tid + i * 256;
        int r = idx >> 4, c = idx & 15;
        uint32_t off = (uint32_t)r * 256 + (uint32_t)((c ^ (r & 7)) << 4);
        cpa16(dst_s + off, base + (size_t)r * 256 + c * 16);
    }
}

// ---------------------------------------------------------------------------
// Fused prep: per block = 8 rows (warp each). Normalizes the 16 centers into
// smem (redundant per block, trivial), splits the row to bf16 hi/lo, computes
// squared norm, init mined arrays, and computes dc = min_p dist(x, cn_p).
__global__ void k_split(const float* __restrict__ X, const float* __restrict__ C) {
    __shared__ float cn_s[P][D];
    const int tid = threadIdx.x, wid = tid >> 5, lane = tid & 31;

    // Normalize centers (warp wid handles centers wid, wid+8).
    #pragma unroll
    for (int cc = wid; cc < P; cc += 8) {
        float4 v = ((const float4*)(C + (size_t)cc * D))[lane];
        float s = v.x * v.x + v.y * v.y + v.z * v.z + v.w * v.w;
        #pragma unroll
        for (int o = 16; o; o >>= 1) s += __shfl_xor_sync(0xffffffffu, s, o);
        float inv = 1.0f / sqrtf(s);
        float* dst = &cn_s[cc][lane * 4];
        dst[0] = v.x * inv; dst[1] = v.y * inv; dst[2] = v.z * inv; dst[3] = v.w * inv;
    }

    const int w = blockIdx.x * 8 + wid;   // this warp's row
    float4 v = ((const float4*)X)[(size_t)w * (D / 4) + lane];

    // bf16 hi/lo split
    __nv_bfloat16 h0 = __float2bfloat16(v.x), h1 = __float2bfloat16(v.y);
    __nv_bfloat16 h2 = __float2bfloat16(v.z), h3 = __float2bfloat16(v.w);
    __nv_bfloat16 l0 = __float2bfloat16(v.x - __bfloat162float(h0));
    __nv_bfloat16 l1 = __float2bfloat16(v.y - __bfloat162float(h1));
    __nv_bfloat16 l2 = __float2bfloat16(v.z - __bfloat162float(h2));
    __nv_bfloat16 l3 = __float2bfloat16(v.w - __bfloat162float(h3));
    size_t o = (size_t)w * (D / 2) + lane * 2;
    ((__nv_bfloat162*)g_xhi)[o]     = __nv_bfloat162(h0, h1);
    ((__nv_bfloat162*)g_xhi)[o + 1] = __nv_bfloat162(h2, h3);
    ((__nv_bfloat162*)g_xlo)[o]     = __nv_bfloat162(l0, l1);
    ((__nv_bfloat162*)g_xlo)[o + 1] = __nv_bfloat162(l2, l3);

    float s = v.x * v.x + v.y * v.y + v.z * v.z + v.w * v.w;
    #pragma unroll
    for (int off = 16; off; off >>= 1) s += __shfl_xor_sync(0xffffffffu, s, off);

    __syncthreads();

    // dc = min over 16 normalized centers of clamp(sqrt(||x||^2 - 2 x.c + 1))
    float dmin = FINF;
    #pragma unroll
    for (int p = 0; p < P; p++) {
        const float* cp = &cn_s[p][lane * 4];
        float dp = v.x * cp[0] + v.y * cp[1] + v.z * cp[2] + v.w * cp[3];
        #pragma unroll
        for (int off = 16; off; off >>= 1) dp += __shfl_xor_sync(0xffffffffu, dp, off);
        float d2 = fmaf(-2.0f, dp, s + 1.0f);
        float dcv = fmaxf(sqrtf(fmaxf(d2, 0.0f)), EPSF);
        dmin = fminf(dmin, dcv);
    }
    if (lane == 0) { g_sq[w] = s; g_maxp[w] = 0; g_minn[w] = INFBITS; g_dc[w] = dmin; }
}

// ---------------------------------------------------------------------------
// Symmetric mining with register-resident A fragments.
// 256 threads, 8 warps: warp (wid&3)->32-row M block, (wid>>2)->64-col N half.
__global__ void __launch_bounds__(256, 1)
k_main(const int* __restrict__ T) {
    extern __shared__ __align__(1024) char smem[];
    __shared__ int   tCol[2][BN];
    __shared__ float sqCol[2][BN];
    __shared__ int   s_J[2];

    const int tid  = threadIdx.x;
    const int wid  = tid >> 5;
    const int lane = tid & 31;
    const int mw   = wid & 3;
    const int nh   = wid >> 2;
    const int wm0  = mw * 32;
    const int wn0  = nh * 64;
    const int I    = blockIdx.x;
    const int sch  = blockIdx.y;
    const int kbeg = sch ? 17 : 0;
    const int kcnt = sch ? 16 : 17;
    const int row0 = I * BM;
    const uint32_t sb = smem_u32(smem);

    float sqr[2][2]; int trow[2][2];
    #pragma unroll
    for (int i = 0; i < 2; i++)
        #pragma unroll
        for (int h = 0; h < 2; h++) {
            int gr = row0 + wm0 + i * 16 + h * 8 + (lane >> 2);
            sqr[i][h] = g_sq[gr];
            trow[i][h] = T[gr];
        }

    uint32_t a_rowoff[2], b_coloff[4];
    const uint32_t a_chk = (uint32_t)(lane >> 4);
    const uint32_t b_chk = (uint32_t)((lane >> 3) & 1);
    #pragma unroll
    for (int i = 0; i < 2; i++) {
        uint32_t r = wm0 + i * 16 + (lane & 7) + ((lane >> 3) & 1) * 8;
        a_rowoff[i] = (r * 256) | ((r & 7) << 28);
    }
    #pragma unroll
    for (int jj = 0; jj < 4; jj++) {
        uint32_t c = wn0 + jj * 16 + (lane & 7) + (lane >> 4) * 8;
        b_coloff[jj] = (c * 256) | ((c & 7) << 28);
    }

    // Prologue: A hi/lo + B0 hi/lo
    cpa_tile(sb + SMA_HI, g_xhi, row0, tid);
    cpa_tile(sb + SMA_LO, g_xlo, row0, tid);
    {
        int J0 = (I + kbeg) & (NB - 1);
        cpa_tile(sb + SMB0,          g_xhi, J0 * BN, tid);
        cpa_tile(sb + SMB0 + 32768u, g_xlo, J0 * BN, tid);
        if (tid < BN) { tCol[0][tid] = T[J0 * BN + tid]; sqCol[0][tid] = g_sq[J0 * BN + tid]; }
        if (tid == 0) s_J[0] = J0;
    }
    CPA_COMMIT();
    CPA_WAIT(0);
    __syncthreads();

    // Load ALL A fragments into registers once (128 regs/thread).
    uint32_t aF_hi[8][2][4], aF_lo[8][2][4];
    #pragma unroll
    for (int ks = 0; ks < 8; ks++) {
        const uint32_t achunk = (uint32_t)(2 * ks) + a_chk;
        #pragma unroll
        for (int i = 0; i < 2; i++) {
            uint32_t ro = a_rowoff[i];
            uint32_t off = (ro & 0x0FFFFFFFu) + ((achunk ^ (ro >> 28)) << 4);
            ldsm4(aF_hi[ks][i], sb + SMA_HI + off);
            ldsm4(aF_lo[ks][i], sb + SMA_LO + off);
        }
    }

    float mp[2][2], mn[2][2];
    #pragma unroll
    for (int i = 0; i < 2; i++)
        #pragma unroll
        for (int h = 0; h < 2; h++) { mp[i][h] = -1.0f; mn[i][h] = FINF; }

    for (int t = 0; t < kcnt; t++) {
        const uint32_t buf = (uint32_t)(t & 1);
        // B(t) resident here. Prefetch B(t+1).
        if (t + 1 < kcnt) {
            int J1 = (I + kbeg + t + 1) & (NB - 1);
            cpa_tile(sb + SMB0 + (buf ^ 1) * SMB_SZ,          g_xhi, J1 * BN, tid);
            cpa_tile(sb + SMB0 + (buf ^ 1) * SMB_SZ + 32768u, g_xlo, J1 * BN, tid);
            CPA_COMMIT();
            if (tid < BN) {
                tCol[buf ^ 1][tid] = T[J1 * BN + tid];
                sqCol[buf ^ 1][tid] = g_sq[J1 * BN + tid];
            }
            if (tid == 0) s_J[buf ^ 1] = J1;
        }

        float acc[2][8][4];
        #pragma unroll
        for (int i = 0; i < 2; i++)
            #pragma unroll
            for (int j = 0; j < 8; j++)
                #pragma unroll
                for (int e = 0; e < 4; e++) acc[i][j][e] = 0.0f;

        const uint32_t bb_hi = sb + SMB0 + buf * SMB_SZ;
        const uint32_t bb_lo = bb_hi + 32768u;

        #pragma unroll
        for (int ks = 0; ks < 8; ks++) {
            uint32_t b[4][4];
            const uint32_t bchunk = (uint32_t)(2 * ks) + b_chk;
            uint32_t boff[4];
            #pragma unroll
            for (int jj = 0; jj < 4; jj++) {
                uint32_t co = b_coloff[jj];
                boff[jj] = (co & 0x0FFFFFFFu) + ((bchunk ^ (co >> 28)) << 4);
                ldsm4(b[jj], bb_hi + boff[jj]);
            }
            // hi*hi and lo*hi both consume b_hi
            #pragma unroll
            for (int i = 0; i < 2; i++)
                #pragma unroll
                for (int jj = 0; jj < 4; jj++) {
                    mma16816(acc[i][2 * jj],     aF_hi[ks][i], &b[jj][0]);
                    mma16816(acc[i][2 * jj + 1], aF_hi[ks][i], &b[jj][2]);
                }
            #pragma unroll
            for (int i = 0; i < 2; i++)
                #pragma unroll
                for (int jj = 0; jj < 4; jj++) {
                    mma16816(acc[i][2 * jj],     aF_lo[ks][i], &b[jj][0]);
                    mma16816(acc[i][2 * jj + 1], aF_lo[ks][i], &b[jj][2]);
                }
            // reload same regs with b_lo; hi*lo
            #pragma unroll
            for (int jj = 0; jj < 4; jj++) ldsm4(b[jj], bb_lo + boff[jj]);
            #pragma unroll
            for (int i = 0; i < 2; i++)
                #pragma unroll
                for (int jj = 0; jj < 4; jj++) {
                    mma16816(acc[i][2 * jj],     aF_hi[ks][i], &b[jj][0]);
                    mma16816(acc[i][2 * jj + 1], aF_hi[ks][i], &b[jj][2]);
                }
        }

        // Fused mining; col stats per j to bound register pressure.
        #pragma unroll
        for (int j = 0; j < 8; j++) {
            int cb = wn0 + j * 8 + (lane & 3) * 2;
            int tc0 = tCol[buf][cb], tc1 = tCol[buf][cb + 1];
            float sc0 = sqCol[buf][cb], sc1 = sqCol[buf][cb + 1];
            float cmax0 = -1.0f, cmax1 = -1.0f, cmin0 = FINF, cmin1 = FINF;
            #pragma unroll
            for (int i = 0; i < 2; i++)
                #pragma unroll
                for (int h = 0; h < 2; h++) {
                    float d0 = fmaxf(fmaf(-2.0f, acc[i][j][2 * h],     sqr[i][h] + sc0), 0.0f);
                    float d1 = fmaxf(fmaf(-2.0f, acc[i][j][2 * h + 1], sqr[i][h] + sc1), 0.0f);
                    if (trow[i][h] == tc0) { mp[i][h] = fmaxf(mp[i][h], d0);
                                             cmax0 = fmaxf(cmax0, d0); }
                    else                   { mn[i][h] = fminf(mn[i][h], d0);
                                             cmin0 = fminf(cmin0, d0); }
                    if (trow[i][h] == tc1) { mp[i][h] = fmaxf(mp[i][h], d1);
                                             cmax1 = fmaxf(cmax1, d1); }
                    else                   { mn[i][h] = fminf(mn[i][h], d1);
                                             cmin1 = fminf(cmin1, d1); }
                }
            #pragma unroll
            for (int o = 4; o <= 16; o <<= 1) {
                cmax0 = fmaxf(cmax0, __shfl_xor_sync(0xffffffffu, cmax0, o));
                cmin0 = fminf(cmin0, __shfl_xor_sync(0xffffffffu, cmin0, o));
                cmax1 = fmaxf(cmax1, __shfl_xor_sync(0xffffffffu, cmax1, o));
                cmin1 = fminf(cmin1, __shfl_xor_sync(0xffffffffu, cmin1, o));
            }
            if (lane < 4) {
                int gcol = s_J[buf] * BN + wn0 + j * 8 + lane * 2;
                atomicMax(&g_maxp[gcol], __float_as_int(cmax0));
                atomicMin(&g_minn[gcol], __float_as_int(cmin0));
                atomicMax(&g_maxp[gcol + 1], __float_as_int(cmax1));
                atomicMin(&g_minn[gcol + 1], __float_as_int(cmin1));
            }
        }

        if (t + 1 < kcnt) CPA_WAIT(0);
        __syncthreads();
    }

    // Row stats: reduce over 4 lanes/row, then order-independent atomics.
    #pragma unroll
    for (int i = 0; i < 2; i++)
        #pragma unroll
        for (int h = 0; h < 2; h++) {
            #pragma unroll
            for (int o = 1; o <= 2; o <<= 1) {
                mp[i][h] = fmaxf(mp[i][h], __shfl_xor_sync(0xffffffffu, mp[i][h], o));
                mn[i][h] = fminf(mn[i][h], __shfl_xor_sync(0xffffffffu, mn[i][h], o));
            }
            if ((lane & 3) == 0) {
                int gr = row0 + wm0 + i * 16 + h * 8 + (lane >> 2);
                atomicMax(&g_maxp[gr], __float_as_int(mp[i][h]));
                atomicMin(&g_minn[gr], __float_as_int(mn[i][h]));
            }
        }
}

// ---------------------------------------------------------------------------
// Final loss: one block, deterministic fixed-order accumulation + tree sum.
__global__ void k_loss(float* __restrict__ out) {
    __shared__ float sh[1024];
    const int t = threadIdx.x;
    float sum = 0.0f;
    #pragma unroll
    for (int k = 0; k < N / 1024; k++) {
        int r = t + k * 1024;
        float mpv = __int_as_float(g_maxp[r]);
        float mnv = __int_as_float(g_minn[r]);
        float dap = sqrtf(fmaxf(mpv, EPSF));
        float dan = isinf(mnv) ? (dap + MARGINF) : sqrtf(fmaxf(mnv, EPSF));
        dan = fminf(dan, g_dc[r]);
        sum += fmaxf(dap - dan + MARGINF, 0.0f);
    }
    sh[t] = sum;
    __syncthreads();
    for (int s = 512; s; s >>= 1) {
        if (t < s) sh[t] += sh[t + s];
        __syncthreads();
    }
    if (t == 0) out[0] = sh[0] / (float)N;
}

// ---------------------------------------------------------------------------
extern "C" void kernel_launch(void* const* d_in, const int* in_sizes, int n_in,
                              void* d_out, int out_size) {
    const float* X = (const float*)d_in[0];
    const int*   T = (const int*)d_in[1];
    const float* C = (const float*)d_in[2];
    float* out = (float*)d_out;

    size_t smem = 196608;
    cudaFuncSetAttribute(k_main, cudaFuncAttributeMaxDynamicSharedMemorySize, (int)smem);

    k_split<<<N / 8, 256>>>(X, C);
    k_main<<<dim3(NB, 2), 256, smem>>>(T);
    k_loss<<<1, 1024>>>(out);
}

// round 10
// speedup vs baseline: 1.0028x; 1.0028x over previous
#include <cuda_runtime.h>
#include <cuda_bf16.h>
#include <cstdint>

#define N       8192
#define D       128
#define BM      128
#define BN      128
#define NB      64
#define P       16
#define MARGINF 1.0f
#define EPSF    1e-12f
#define FINF    __int_as_float(0x7f800000)
#define INFBITS 0x7f800000

// smem layout (dynamic, 192KB): A hi | A lo | B buf0 (hi|lo) | B buf1 (hi|lo)
#define SMA_HI  0u
#define SMA_LO  32768u
#define SMB0    65536u
#define SMB_SZ  65536u

// Scratch (no allocation allowed -> device globals)
__device__ float g_sq[N];
__device__ int   g_maxp[N];     // float bits, order-independent atomics
__device__ int   g_minn[N];
__device__ float g_dc[N];       // min distance to normalized centers
__device__ __nv_bfloat16 g_xhi[N * D];
__device__ __nv_bfloat16 g_xlo[N * D];

// ---------------------------------------------------------------------------
static __device__ __forceinline__ uint32_t smem_u32(const void* p) {
    uint32_t a;
    asm("{ .reg .u64 t; cvta.to.shared.u64 t, %1; cvt.u32.u64 %0, t; }" : "=r"(a) : "l"(p));
    return a;
}
static __device__ __forceinline__ void ldsm4(uint32_t* r, uint32_t addr) {
    asm volatile("ldmatrix.sync.aligned.m8n8.x4.shared.b16 {%0,%1,%2,%3}, [%4];"
                 : "=r"(r[0]), "=r"(r[1]), "=r"(r[2]), "=r"(r[3]) : "r"(addr));
}
static __device__ __forceinline__ void mma16816(float* c, const uint32_t* a,
                                                const uint32_t* b) {
    asm volatile("mma.sync.aligned.m16n8k16.row.col.f32.bf16.bf16.f32 "
                 "{%0,%1,%2,%3}, {%4,%5,%6,%7}, {%8,%9}, {%0,%1,%2,%3};"
                 : "+f"(c[0]), "+f"(c[1]), "+f"(c[2]), "+f"(c[3])
                 : "r"(a[0]), "r"(a[1]), "r"(a[2]), "r"(a[3]), "r"(b[0]), "r"(b[1]));
}
static __device__ __forceinline__ void cpa16(uint32_t dst, const void* src) {
    asm volatile("cp.async.cg.shared.global [%0], [%1], 16;" :: "r"(dst), "l"(src) : "memory");
}
#define CPA_COMMIT() asm volatile("cp.async.commit_group;" ::: "memory")
#define CPA_WAIT(n)  asm volatile("cp.async.wait_group %0;" :: "n"(n) : "memory")

// 128x128 bf16 tile -> smem, 256B rows, 16B-chunk xor swizzle (256 threads).
static __device__ __forceinline__ void cpa_tile(uint32_t dst_s,
                                                const __nv_bfloat16* src,
                                                int row0, int tid) {
    const char* base = (const char*)(src + (size_t)row0 * D);
    #pragma unroll
    for (int i = 0; i < 8; i++) {
        int idx = tid + i * 256;
        int r = idx >> 4, c = idx & 15;
        uint32_t off = (uint32_t)r * 256 + (uint32_t)((c ^ (r & 7)) << 4);
        cpa16(dst_s + off, base + (size_t)r * 256 + c * 16);
    }
}

// ---------------------------------------------------------------------------
// Fused prep: per block = 8 rows (warp each). Normalize centers into smem,
// split rows to bf16 hi/lo, squared norm, init mined arrays, dc = min center dist.
__global__ void k_split(const float* __restrict__ X, const float* __restrict__ C) {
    __shared__ float cn_s[P][D];
    const int tid = threadIdx.x, wid = tid >> 5, lane = tid & 31;

    #pragma unroll
    for (int cc = wid; cc < P; cc += 8) {
        float4 v = ((const float4*)(C + (size_t)cc * D))[lane];
        float s = v.x * v.x + v.y * v.y + v.z * v.z + v.w * v.w;
        #pragma unroll
        for (int o = 16; o; o >>= 1) s += __shfl_xor_sync(0xffffffffu, s, o);
        float inv = 1.0f / sqrtf(s);
        float* dst = &cn_s[cc][lane * 4];
        dst[0] = v.x * inv; dst[1] = v.y * inv; dst[2] = v.z * inv; dst[3] = v.w * inv;
    }

    const int w = blockIdx.x * 8 + wid;
    float4 v = ((const float4*)X)[(size_t)w * (D / 4) + lane];

    __nv_bfloat16 h0 = __float2bfloat16(v.x), h1 = __float2bfloat16(v.y);
    __nv_bfloat16 h2 = __float2bfloat16(v.z), h3 = __float2bfloat16(v.w);
    __nv_bfloat16 l0 = __float2bfloat16(v.x - __bfloat162float(h0));
    __nv_bfloat16 l1 = __float2bfloat16(v.y - __bfloat162float(h1));
    __nv_bfloat16 l2 = __float2bfloat16(v.z - __bfloat162float(h2));
    __nv_bfloat16 l3 = __float2bfloat16(v.w - __bfloat162float(h3));
    size_t o = (size_t)w * (D / 2) + lane * 2;
    ((__nv_bfloat162*)g_xhi)[o]     = __nv_bfloat162(h0, h1);
    ((__nv_bfloat162*)g_xhi)[o + 1] = __nv_bfloat162(h2, h3);
    ((__nv_bfloat162*)g_xlo)[o]     = __nv_bfloat162(l0, l1);
    ((__nv_bfloat162*)g_xlo)[o + 1] = __nv_bfloat162(l2, l3);

    float s = v.x * v.x + v.y * v.y + v.z * v.z + v.w * v.w;
    #pragma unroll
    for (int off = 16; off; off >>= 1) s += __shfl_xor_sync(0xffffffffu, s, off);

    __syncthreads();

    float dmin = FINF;
    #pragma unroll
    for (int p = 0; p < P; p++) {
        const float* cp = &cn_s[p][lane * 4];
        float dp = v.x * cp[0] + v.y * cp[1] + v.z * cp[2] + v.w * cp[3];
        #pragma unroll
        for (int off = 16; off; off >>= 1) dp += __shfl_xor_sync(0xffffffffu, dp, off);
        float d2 = fmaf(-2.0f, dp, s + 1.0f);
        float dcv = fmaxf(sqrtf(fmaxf(d2, 0.0f)), EPSF);
        dmin = fminf(dmin, dcv);
    }
    if (lane == 0) { g_sq[w] = s; g_maxp[w] = 0; g_minn[w] = INFBITS; g_dc[w] = dmin; }
}

// ---------------------------------------------------------------------------
// Symmetric mining. 256 threads, 8 warps: warp (wid&3)->32-row M block,
// (wid>>2)->64-col N half. Fragment double-buffering across k-steps.
__global__ void __launch_bounds__(256, 1)
k_main(const int* __restrict__ T) {
    extern __shared__ __align__(1024) char smem[];
    __shared__ int   tCol[2][BN];
    __shared__ float sqCol[2][BN];
    __shared__ int   s_J[2];

    const int tid  = threadIdx.x;
    const int wid  = tid >> 5;
    const int lane = tid & 31;
    const int mw   = wid & 3;
    const int nh   = wid >> 2;
    const int wm0  = mw * 32;
    const int wn0  = nh * 64;
    const int I    = blockIdx.x;
    const int sch  = blockIdx.y;
    const int kbeg = sch ? 17 : 0;
    const int kcnt = sch ? 16 : 17;
    const int row0 = I * BM;
    const uint32_t sb = smem_u32(smem);

    float sqr[2][2]; int trow[2][2];
    #pragma unroll
    for (int i = 0; i < 2; i++)
        #pragma unroll
        for (int h = 0; h < 2; h++) {
            int gr = row0 + wm0 + i * 16 + h * 8 + (lane >> 2);
            sqr[i][h] = g_sq[gr];
            trow[i][h] = T[gr];
        }

    uint32_t a_rowoff[2], b_coloff[4];
    const uint32_t a_chk = (uint32_t)(lane >> 4);
    const uint32_t b_chk = (uint32_t)((lane >> 3) & 1);
    #pragma unroll
    for (int i = 0; i < 2; i++) {
        uint32_t r = wm0 + i * 16 + (lane & 7) + ((lane >> 3) & 1) * 8;
        a_rowoff[i] = (r * 256) | ((r & 7) << 28);
    }
    #pragma unroll
    for (int jj = 0; jj < 4; jj++) {
        uint32_t c = wn0 + jj * 16 + (lane & 7) + (lane >> 4) * 8;
        b_coloff[jj] = (c * 256) | ((c & 7) << 28);
    }

    // Prologue: A hi/lo + B0 hi/lo + labels
    cpa_tile(sb + SMA_HI, g_xhi, row0, tid);
    cpa_tile(sb + SMA_LO, g_xlo, row0, tid);
    {
        int J0 = (I + kbeg) & (NB - 1);
        cpa_tile(sb + SMB0,          g_xhi, J0 * BN, tid);
        cpa_tile(sb + SMB0 + 32768u, g_xlo, J0 * BN, tid);
        if (tid < BN) { tCol[0][tid] = T[J0 * BN + tid]; sqCol[0][tid] = g_sq[J0 * BN + tid]; }
        if (tid == 0) s_J[0] = J0;
    }
    CPA_COMMIT();

    float mp[2][2], mn[2][2];
    #pragma unroll
    for (int i = 0; i < 2; i++)
        #pragma unroll
        for (int h = 0; h < 2; h++) { mp[i][h] = -1.0f; mn[i][h] = FINF; }

    for (int t = 0; t < kcnt; t++) {
        const uint32_t buf = (uint32_t)(t & 1);
        CPA_WAIT(0);
        __syncthreads();        // tile t resident; all warps done with buf^1

        if (t + 1 < kcnt) {
            int J1 = (I + kbeg + t + 1) & (NB - 1);
            cpa_tile(sb + SMB0 + (buf ^ 1) * SMB_SZ,          g_xhi, J1 * BN, tid);
            cpa_tile(sb + SMB0 + (buf ^ 1) * SMB_SZ + 32768u, g_xlo, J1 * BN, tid);
            CPA_COMMIT();
            if (tid < BN) {
                tCol[buf ^ 1][tid] = T[J1 * BN + tid];
                sqCol[buf ^ 1][tid] = g_sq[J1 * BN + tid];
            }
            if (tid == 0) s_J[buf ^ 1] = J1;
        }

        float acc[2][8][4];
        #pragma unroll
        for (int i = 0; i < 2; i++)
            #pragma unroll
            for (int j = 0; j < 8; j++)
                #pragma unroll
                for (int e = 0; e < 4; e++) acc[i][j][e] = 0.0f;

        const uint32_t ab_hi = sb + SMA_HI;
        const uint32_t ab_lo = sb + SMA_LO;
        const uint32_t bb_hi = sb + SMB0 + buf * SMB_SZ;
        const uint32_t bb_lo = bb_hi + 32768u;

        // Fragment double buffers: slot = ks & 1.
        uint32_t aH[2][2][4], aL[2][2][4], bH[2][4][4], bL[2][4][4];

        // Load k-step 0 into slot 0.
        {
            const uint32_t achunk = a_chk, bchunk = b_chk;
            #pragma unroll
            for (int i = 0; i < 2; i++) {
                uint32_t ro = a_rowoff[i];
                uint32_t off = (ro & 0x0FFFFFFFu) + ((achunk ^ (ro >> 28)) << 4);
                ldsm4(aH[0][i], ab_hi + off);
                ldsm4(aL[0][i], ab_lo + off);
            }
            #pragma unroll
            for (int jj = 0; jj < 4; jj++) {
                uint32_t co = b_coloff[jj];
                uint32_t off = (co & 0x0FFFFFFFu) + ((bchunk ^ (co >> 28)) << 4);
                ldsm4(bH[0][jj], bb_hi + off);
                ldsm4(bL[0][jj], bb_lo + off);
            }
        }

        #pragma unroll
        for (int ks = 0; ks < 8; ks++) {
            const int cur = ks & 1, nxt = cur ^ 1;
            // Prefetch k-step ks+1 into the other slot (independent of MMAs).
            if (ks < 7) {
                const uint32_t achunk = (uint32_t)(2 * (ks + 1)) + a_chk;
                const uint32_t bchunk = (uint32_t)(2 * (ks + 1)) + b_chk;
                #pragma unroll
                for (int i = 0; i < 2; i++) {
                    uint32_t ro = a_rowoff[i];
                    uint32_t off = (ro & 0x0FFFFFFFu) + ((achunk ^ (ro >> 28)) << 4);
                    ldsm4(aH[nxt][i], ab_hi + off);
                    ldsm4(aL[nxt][i], ab_lo + off);
                }
                #pragma unroll
                for (int jj = 0; jj < 4; jj++) {
                    uint32_t co = b_coloff[jj];
                    uint32_t off = (co & 0x0FFFFFFFu) + ((bchunk ^ (co >> 28)) << 4);
                    ldsm4(bH[nxt][jj], bb_hi + off);
                    ldsm4(bL[nxt][jj], bb_lo + off);
                }
            }
            // 48 MMAs on slot cur; same-acc writes spaced 16 apart.
            #pragma unroll
            for (int i = 0; i < 2; i++)
                #pragma unroll
                for (int jj = 0; jj < 4; jj++) {
                    mma16816(acc[i][2 * jj],     aH[cur][i], &bH[cur][jj][0]);
                    mma16816(acc[i][2 * jj + 1], aH[cur][i], &bH[cur][jj][2]);
                }
            #pragma unroll
            for (int i = 0; i < 2; i++)
                #pragma unroll
                for (int jj = 0; jj < 4; jj++) {
                    mma16816(acc[i][2 * jj],     aH[cur][i], &bL[cur][jj][0]);
                    mma16816(acc[i][2 * jj + 1], aH[cur][i], &bL[cur][jj][2]);
                }
            #pragma unroll
            for (int i = 0; i < 2; i++)
                #pragma unroll
                for (int jj = 0; jj < 4; jj++) {
                    mma16816(acc[i][2 * jj],     aL[cur][i], &bH[cur][jj][0]);
                    mma16816(acc[i][2 * jj + 1], aL[cur][i], &bH[cur][jj][2]);
                }
        }

        // Fused mining; per-j col stats -> butterflies -> global atomics.
        #pragma unroll
        for (int j = 0; j < 8; j++) {
            int cb = wn0 + j * 8 + (lane & 3) * 2;
            int tc0 = tCol[buf][cb], tc1 = tCol[buf][cb + 1];
            float sc0 = sqCol[buf][cb], sc1 = sqCol[buf][cb + 1];
            float cmax0 = -1.0f, cmax1 = -1.0f, cmin0 = FINF, cmin1 = FINF;
            #pragma unroll
            for (int i = 0; i < 2; i++)
                #pragma unroll
                for (int h = 0; h < 2; h++) {
                    float d0 = fmaxf(fmaf(-2.0f, acc[i][j][2 * h],     sqr[i][h] + sc0), 0.0f);
                    float d1 = fmaxf(fmaf(-2.0f, acc[i][j][2 * h + 1], sqr[i][h] + sc1), 0.0f);
                    if (trow[i][h] == tc0) { mp[i][h] = fmaxf(mp[i][h], d0);
                                             cmax0 = fmaxf(cmax0, d0); }
                    else                   { mn[i][h] = fminf(mn[i][h], d0);
                                             cmin0 = fminf(cmin0, d0); }
                    if (trow[i][h] == tc1) { mp[i][h] = fmaxf(mp[i][h], d1);
                                             cmax1 = fmaxf(cmax1, d1); }
                    else                   { mn[i][h] = fminf(mn[i][h], d1);
                                             cmin1 = fminf(cmin1, d1); }
                }
            #pragma unroll
            for (int o = 4; o <= 16; o <<= 1) {
                cmax0 = fmaxf(cmax0, __shfl_xor_sync(0xffffffffu, cmax0, o));
                cmin0 = fminf(cmin0, __shfl_xor_sync(0xffffffffu, cmin0, o));
                cmax1 = fmaxf(cmax1, __shfl_xor_sync(0xffffffffu, cmax1, o));
                cmin1 = fminf(cmin1, __shfl_xor_sync(0xffffffffu, cmin1, o));
            }
            if (lane < 4) {
                int gcol = s_J[buf] * BN + wn0 + j * 8 + lane * 2;
                atomicMax(&g_maxp[gcol], __float_as_int(cmax0));
                atomicMin(&g_minn[gcol], __float_as_int(cmin0));
                atomicMax(&g_maxp[gcol + 1], __float_as_int(cmax1));
                atomicMin(&g_minn[gcol + 1], __float_as_int(cmin1));
            }
        }
    }

    // Row stats: reduce over 4 lanes/row, then order-independent atomics.
    #pragma unroll
    for (int i = 0; i < 2; i++)
        #pragma unroll
        for (int h = 0; h < 2; h++) {
            #pragma unroll
            for (int o = 1; o <= 2; o <<= 1) {
                mp[i][h] = fmaxf(mp[i][h], __shfl_xor_sync(0xffffffffu, mp[i][h], o));
                mn[i][h] = fminf(mn[i][h], __shfl_xor_sync(0xffffffffu, mn[i][h], o));
            }
            if ((lane & 3) == 0) {
                int gr = row0 + wm0 + i * 16 + h * 8 + (lane >> 2);
                atomicMax(&g_maxp[gr], __float_as_int(mp[i][h]));
                atomicMin(&g_minn[gr], __float_as_int(mn[i][h]));
            }
        }
}

// ---------------------------------------------------------------------------
// Final loss: one block, deterministic fixed-order accumulation + tree sum.
__global__ void k_loss(float* __restrict__ out) {
    __shared__ float sh[1024];
    const int t = threadIdx.x;
    float sum = 0.0f;
    #pragma unroll
    for (int k = 0; k < N / 1024; k++) {
        int r = t + k * 1024;
        float mpv = __int_as_float(g_maxp[r]);
        float mnv = __int_as_float(g_minn[r]);
        float dap = sqrtf(fmaxf(mpv, EPSF));
        float dan = isinf(mnv) ? (dap + MARGINF) : sqrtf(fmaxf(mnv, EPSF));
        dan = fminf(dan, g_dc[r]);
        sum += fmaxf(dap - dan + MARGINF, 0.0f);
    }
    sh[t] = sum;
    __syncthreads();
    for (int s = 512; s; s >>= 1) {
        if (t < s) sh[t] += sh[t + s];
        __syncthreads();
    }
    if (t == 0) out[0] = sh[0] / (float)N;
}

// ---------------------------------------------------------------------------
extern "C" void kernel_launch(void* const* d_in, const int* in_sizes, int n_in,
                              void* d_out, int out_size) {
    const float* X = (const float*)d_in[0];
    const int*   T = (const int*)d_in[1];
    const float* C = (const float*)d_in[2];
    float* out = (float*)d_out;

    size_t smem = 196608;
    cudaFuncSetAttribute(k_main, cudaFuncAttributeMaxDynamicSharedMemorySize, (int)smem);

    k_split<<<N / 8, 256>>>(X, C);
    k_main<<<dim3(NB, 2), 256, smem>>>(T);
    k_loss<<<1, 1024>>>(out);
}

// round 11
// speedup vs baseline: 1.0406x; 1.0378x over previous
#include <cuda_runtime.h>
#include <cuda_bf16.h>
#include <cstdint>

#define N       8192
#define D       128
#define BM      128
#define BN      128
#define NB      64
#define P       16
#define MARGINF 1.0f
#define EPSF    1e-12f
#define FINF    __int_as_float(0x7f800000)
#define INFBITS 0x7f800000

// smem layout (dynamic, 192KB): A hi | A lo | B buf0 (hi|lo) | B buf1 (hi|lo)
#define SMA_HI  0u
#define SMA_LO  32768u
#define SMB0    65536u
#define SMB_SZ  65536u

// Scratch (no allocation allowed -> device globals)
__device__ float g_sq[N];
__device__ int   g_maxp[N];     // float bits, order-independent atomics
__device__ int   g_minn[N];
__device__ float g_dc[N];       // min distance to normalized centers
__device__ __nv_bfloat16 g_xhi[N * D];
__device__ __nv_bfloat16 g_xlo[N * D];

// ---------------------------------------------------------------------------
static __device__ __forceinline__ uint32_t smem_u32(const void* p) {
    uint32_t a;
    asm("{ .reg .u64 t; cvta.to.shared.u64 t, %1; cvt.u32.u64 %0, t; }" : "=r"(a) : "l"(p));
    return a;
}
static __device__ __forceinline__ void ldsm4(uint32_t* r, uint32_t addr) {
    asm volatile("ldmatrix.sync.aligned.m8n8.x4.shared.b16 {%0,%1,%2,%3}, [%4];"
                 : "=r"(r[0]), "=r"(r[1]), "=r"(r[2]), "=r"(r[3]) : "r"(addr));
}
static __device__ __forceinline__ void mma16816(float* c, const uint32_t* a,
                                                const uint32_t* b) {
    asm volatile("mma.sync.aligned.m16n8k16.row.col.f32.bf16.bf16.f32 "
                 "{%0,%1,%2,%3}, {%4,%5,%6,%7}, {%8,%9}, {%0,%1,%2,%3};"
                 : "+f"(c[0]), "+f"(c[1]), "+f"(c[2]), "+f"(c[3])
                 : "r"(a[0]), "r"(a[1]), "r"(a[2]), "r"(a[3]), "r"(b[0]), "r"(b[1]));
}
static __device__ __forceinline__ void cpa16(uint32_t dst, const void* src) {
    asm volatile("cp.async.cg.shared.global [%0], [%1], 16;" :: "r"(dst), "l"(src) : "memory");
}
#define CPA_COMMIT() asm volatile("cp.async.commit_group;" ::: "memory")
#define CPA_WAIT(n)  asm volatile("cp.async.wait_group %0;" :: "n"(n) : "memory")

// 128x128 bf16 tile -> smem, 256B rows, 16B-chunk xor swizzle (512 threads).
static __device__ __forceinline__ void cpa_tile(uint32_t dst_s,
                                                const __nv_bfloat16* src,
                                                int row0, int tid) {
    const char* base = (const char*)(src + (size_t)row0 * D);
    #pragma unroll
    for (int i = 0; i < 4; i++) {
        int idx = tid + i * 512;
        int r = idx >> 4, c = idx & 15;
        uint32_t off = (uint32_t)r * 256 + (uint32_t)((c ^ (r & 7)) << 4);
        cpa16(dst_s + off, base + (size_t)r * 256 + c * 16);
    }
}

// ---------------------------------------------------------------------------
// Fused prep: per block = 8 rows (warp each). Normalize centers into smem,
// split rows to bf16 hi/lo, squared norm, init mined arrays, dc = min center dist.
__global__ void k_split(const float* __restrict__ X, const float* __restrict__ C) {
    __shared__ float cn_s[P][D];
    const int tid = threadIdx.x, wid = tid >> 5, lane = tid & 31;

    #pragma unroll
    for (int cc = wid; cc < P; cc += 8) {
        float4 v = ((const float4*)(C + (size_t)cc * D))[lane];
        float s = v.x * v.x + v.y * v.y + v.z * v.z + v.w * v.w;
        #pragma unroll
        for (int o = 16; o; o >>= 1) s += __shfl_xor_sync(0xffffffffu, s, o);
        float inv = 1.0f / sqrtf(s);
        float* dst = &cn_s[cc][lane * 4];
        dst[0] = v.x * inv; dst[1] = v.y * inv; dst[2] = v.z * inv; dst[3] = v.w * inv;
    }

    const int w = blockIdx.x * 8 + wid;
    float4 v = ((const float4*)X)[(size_t)w * (D / 4) + lane];

    __nv_bfloat16 h0 = __float2bfloat16(v.x), h1 = __float2bfloat16(v.y);
    __nv_bfloat16 h2 = __float2bfloat16(v.z), h3 = __float2bfloat16(v.w);
    __nv_bfloat16 l0 = __float2bfloat16(v.x - __bfloat162float(h0));
    __nv_bfloat16 l1 = __float2bfloat16(v.y - __bfloat162float(h1));
    __nv_bfloat16 l2 = __float2bfloat16(v.z - __bfloat162float(h2));
    __nv_bfloat16 l3 = __float2bfloat16(v.w - __bfloat162float(h3));
    size_t o = (size_t)w * (D / 2) + lane * 2;
    ((__nv_bfloat162*)g_xhi)[o]     = __nv_bfloat162(h0, h1);
    ((__nv_bfloat162*)g_xhi)[o + 1] = __nv_bfloat162(h2, h3);
    ((__nv_bfloat162*)g_xlo)[o]     = __nv_bfloat162(l0, l1);
    ((__nv_bfloat162*)g_xlo)[o + 1] = __nv_bfloat162(l2, l3);

    float s = v.x * v.x + v.y * v.y + v.z * v.z + v.w * v.w;
    #pragma unroll
    for (int off = 16; off; off >>= 1) s += __shfl_xor_sync(0xffffffffu, s, off);

    __syncthreads();

    float dmin = FINF;
    #pragma unroll
    for (int p = 0; p < P; p++) {
        const float* cp = &cn_s[p][lane * 4];
        float dp = v.x * cp[0] + v.y * cp[1] + v.z * cp[2] + v.w * cp[3];
        #pragma unroll
        for (int off = 16; off; off >>= 1) dp += __shfl_xor_sync(0xffffffffu, dp, off);
        float d2 = fmaf(-2.0f, dp, s + 1.0f);
        float dcv = fmaxf(sqrtf(fmaxf(d2, 0.0f)), EPSF);
        dmin = fminf(dmin, dcv);
    }
    if (lane == 0) { g_sq[w] = s; g_maxp[w] = 0; g_minn[w] = INFBITS; g_dc[w] = dmin; }
}

// ---------------------------------------------------------------------------
// Symmetric mining (R8-measured best): block (I,s) does tiles (I,(I+k)%64).
// 512 threads, 16 warps in a 4x4 grid: warp tile 32 rows x 32 cols.
__global__ void __launch_bounds__(512, 1)
k_main(const int* __restrict__ T) {
    extern __shared__ __align__(1024) char smem[];
    __shared__ int   tCol[2][BN];
    __shared__ float sqCol[2][BN];
    __shared__ int   s_J[2];

    const int tid  = threadIdx.x;
    const int wid  = tid >> 5;
    const int lane = tid & 31;
    const int mw   = wid & 3;          // M-warp (32 rows)
    const int nq   = wid >> 2;         // N-quarter (32 cols)
    const int wm0  = mw * 32;
    const int wn0  = nq * 32;
    const int I    = blockIdx.x;
    const int sch  = blockIdx.y;       // 0: k=0..16, 1: k=17..32
    const int kbeg = sch ? 17 : 0;
    const int kcnt = sch ? 16 : 17;
    const int row0 = I * BM;
    const uint32_t sb = smem_u32(smem);

    float sqr[2][2]; int trow[2][2];
    #pragma unroll
    for (int i = 0; i < 2; i++)
        #pragma unroll
        for (int h = 0; h < 2; h++) {
            int gr = row0 + wm0 + i * 16 + h * 8 + (lane >> 2);
            sqr[i][h] = g_sq[gr];
            trow[i][h] = T[gr];
        }

    uint32_t a_rowoff[2], b_coloff[2];
    const uint32_t a_chk = (uint32_t)(lane >> 4);
    const uint32_t b_chk = (uint32_t)((lane >> 3) & 1);
    #pragma unroll
    for (int i = 0; i < 2; i++) {
        uint32_t r = wm0 + i * 16 + (lane & 7) + ((lane >> 3) & 1) * 8;
        a_rowoff[i] = (r * 256) | ((r & 7) << 28);
    }
    #pragma unroll
    for (int jj = 0; jj < 2; jj++) {
        uint32_t c = wn0 + jj * 16 + (lane & 7) + (lane >> 4) * 8;
        b_coloff[jj] = (c * 256) | ((c & 7) << 28);
    }

    // Prologue
    cpa_tile(sb + SMA_HI, g_xhi, row0, tid);
    cpa_tile(sb + SMA_LO, g_xlo, row0, tid);
    {
        int J0 = (I + kbeg) & (NB - 1);
        cpa_tile(sb + SMB0,          g_xhi, J0 * BN, tid);
        cpa_tile(sb + SMB0 + 32768u, g_xlo, J0 * BN, tid);
        if (tid < BN) { tCol[0][tid] = T[J0 * BN + tid]; sqCol[0][tid] = g_sq[J0 * BN + tid]; }
        if (tid == 0) s_J[0] = J0;
    }
    CPA_COMMIT();

    float mp[2][2], mn[2][2];
    #pragma unroll
    for (int i = 0; i < 2; i++)
        #pragma unroll
        for (int h = 0; h < 2; h++) { mp[i][h] = -1.0f; mn[i][h] = FINF; }

    for (int t = 0; t < kcnt; t++) {
        const uint32_t buf = (uint32_t)(t & 1);
        CPA_WAIT(0);
        __syncthreads();        // tile t resident; everyone done with buf^1

        if (t + 1 < kcnt) {
            int J1 = (I + kbeg + t + 1) & (NB - 1);
            cpa_tile(sb + SMB0 + (buf ^ 1) * SMB_SZ,          g_xhi, J1 * BN, tid);
            cpa_tile(sb + SMB0 + (buf ^ 1) * SMB_SZ + 32768u, g_xlo, J1 * BN, tid);
            CPA_COMMIT();
            if (tid < BN) {
                tCol[buf ^ 1][tid] = T[J1 * BN + tid];
                sqCol[buf ^ 1][tid] = g_sq[J1 * BN + tid];
            }
            if (tid == 0) s_J[buf ^ 1] = J1;
        }

        float acc[2][4][4];
        #pragma unroll
        for (int i = 0; i < 2; i++)
            #pragma unroll
            for (int j = 0; j < 4; j++)
                #pragma unroll
                for (int e = 0; e < 4; e++) acc[i][j][e] = 0.0f;

        const uint32_t ab_hi = sb + SMA_HI;
        const uint32_t ab_lo = sb + SMA_LO;
        const uint32_t bb_hi = sb + SMB0 + buf * SMB_SZ;
        const uint32_t bb_lo = bb_hi + 32768u;

        #pragma unroll
        for (int ks = 0; ks < 8; ks++) {
            uint32_t a_hi[2][4], a_lo[2][4], b_hi[2][4], b_lo[2][4];
            const uint32_t achunk = (uint32_t)(2 * ks) + a_chk;
            const uint32_t bchunk = (uint32_t)(2 * ks) + b_chk;
            #pragma unroll
            for (int i = 0; i < 2; i++) {
                uint32_t ro = a_rowoff[i];
                uint32_t off = (ro & 0x0FFFFFFFu) + ((achunk ^ (ro >> 28)) << 4);
                ldsm4(a_hi[i], ab_hi + off);
                ldsm4(a_lo[i], ab_lo + off);
            }
            #pragma unroll
            for (int jj = 0; jj < 2; jj++) {
                uint32_t co = b_coloff[jj];
                uint32_t off = (co & 0x0FFFFFFFu) + ((bchunk ^ (co >> 28)) << 4);
                ldsm4(b_hi[jj], bb_hi + off);
                ldsm4(b_lo[jj], bb_lo + off);
            }
            // Three sweeps: hi*hi, hi*lo, lo*hi — same-acc writes spaced 8 apart.
            #pragma unroll
            for (int i = 0; i < 2; i++)
                #pragma unroll
                for (int jj = 0; jj < 2; jj++) {
                    mma16816(acc[i][2 * jj],     a_hi[i], &b_hi[jj][0]);
                    mma16816(acc[i][2 * jj + 1], a_hi[i], &b_hi[jj][2]);
                }
            #pragma unroll
            for (int i = 0; i < 2; i++)
                #pragma unroll
                for (int jj = 0; jj < 2; jj++) {
                    mma16816(acc[i][2 * jj],     a_hi[i], &b_lo[jj][0]);
                    mma16816(acc[i][2 * jj + 1], a_hi[i], &b_lo[jj][2]);
                }
            #pragma unroll
            for (int i = 0; i < 2; i++)
                #pragma unroll
                for (int jj = 0; jj < 2; jj++) {
                    mma16816(acc[i][2 * jj],     a_lo[i], &b_hi[jj][0]);
                    mma16816(acc[i][2 * jj + 1], a_lo[i], &b_hi[jj][2]);
                }
        }

        // Fused mining: row stats (registers) + col stats (per tile).
        float cmax[4][2], cmin[4][2];
        #pragma unroll
        for (int j = 0; j < 4; j++) { cmax[j][0] = cmax[j][1] = -1.0f;
                                      cmin[j][0] = cmin[j][1] = FINF; }
        #pragma unroll
        for (int j = 0; j < 4; j++) {
            int cb = wn0 + j * 8 + (lane & 3) * 2;
            int tc0 = tCol[buf][cb], tc1 = tCol[buf][cb + 1];
            float sc0 = sqCol[buf][cb], sc1 = sqCol[buf][cb + 1];
            #pragma unroll
            for (int i = 0; i < 2; i++)
                #pragma unroll
                for (int h = 0; h < 2; h++) {
                    float d0 = fmaxf(fmaf(-2.0f, acc[i][j][2 * h],     sqr[i][h] + sc0), 0.0f);
                    float d1 = fmaxf(fmaf(-2.0f, acc[i][j][2 * h + 1], sqr[i][h] + sc1), 0.0f);
                    if (trow[i][h] == tc0) { mp[i][h] = fmaxf(mp[i][h], d0);
                                             cmax[j][0] = fmaxf(cmax[j][0], d0); }
                    else                   { mn[i][h] = fminf(mn[i][h], d0);
                                             cmin[j][0] = fminf(cmin[j][0], d0); }
                    if (trow[i][h] == tc1) { mp[i][h] = fmaxf(mp[i][h], d1);
                                             cmax[j][1] = fmaxf(cmax[j][1], d1); }
                    else                   { mn[i][h] = fminf(mn[i][h], d1);
                                             cmin[j][1] = fminf(cmin[j][1], d1); }
                }
        }
        // Butterfly over the 8 row-lane-groups, then no-return global atomics.
        #pragma unroll
        for (int j = 0; j < 4; j++)
            #pragma unroll
            for (int e = 0; e < 2; e++) {
                #pragma unroll
                for (int o = 4; o <= 16; o <<= 1) {
                    cmax[j][e] = fmaxf(cmax[j][e], __shfl_xor_sync(0xffffffffu, cmax[j][e], o));
                    cmin[j][e] = fminf(cmin[j][e], __shfl_xor_sync(0xffffffffu, cmin[j][e], o));
                }
            }
        if (lane < 4) {
            int colbase = s_J[buf] * BN + wn0;
            #pragma unroll
            for (int j = 0; j < 4; j++)
                #pragma unroll
                for (int e = 0; e < 2; e++) {
                    int gcol = colbase + j * 8 + lane * 2 + e;
                    atomicMax(&g_maxp[gcol], __float_as_int(cmax[j][e]));
                    atomicMin(&g_minn[gcol], __float_as_int(cmin[j][e]));
                }
        }
    }

    // Row stats: reduce over 4 lanes/row, then order-independent atomics
    // (4 N-quarter warps contribute per row).
    #pragma unroll
    for (int i = 0; i < 2; i++)
        #pragma unroll
        for (int h = 0; h < 2; h++) {
            #pragma unroll
            for (int o = 1; o <= 2; o <<= 1) {
                mp[i][h] = fmaxf(mp[i][h], __shfl_xor_sync(0xffffffffu, mp[i][h], o));
                mn[i][h] = fminf(mn[i][h], __shfl_xor_sync(0xffffffffu, mn[i][h], o));
            }
            if ((lane & 3) == 0) {
                int gr = row0 + wm0 + i * 16 + h * 8 + (lane >> 2);
                atomicMax(&g_maxp[gr], __float_as_int(mp[i][h]));
                atomicMin(&g_minn[gr], __float_as_int(mn[i][h]));
            }
        }
}

// ---------------------------------------------------------------------------
// Final loss: one block, deterministic fixed-order accumulation + tree sum.
__global__ void k_loss(float* __restrict__ out) {
    __shared__ float sh[1024];
    const int t = threadIdx.x;
    float sum = 0.0f;
    #pragma unroll
    for (int k = 0; k < N / 1024; k++) {
        int r = t + k * 1024;
        float mpv = __int_as_float(g_maxp[r]);
        float mnv = __int_as_float(g_minn[r]);
        float dap = sqrtf(fmaxf(mpv, EPSF));
        float dan = isinf(mnv) ? (dap + MARGINF) : sqrtf(fmaxf(mnv, EPSF));
        dan = fminf(dan, g_dc[r]);
        sum += fmaxf(dap - dan + MARGINF, 0.0f);
    }
    sh[t] = sum;
    __syncthreads();
    for (int s = 512; s; s >>= 1) {
        if (t < s) sh[t] += sh[t + s];
        __syncthreads();
    }
    if (t == 0) out[0] = sh[0] / (float)N;
}

// ---------------------------------------------------------------------------
extern "C" void kernel_launch(void* const* d_in, const int* in_sizes, int n_in,
                              void* d_out, int out_size) {
    const float* X = (const float*)d_in[0];
    const int*   T = (const int*)d_in[1];
    const float* C = (const float*)d_in[2];
    float* out = (float*)d_out;

    size_t smem = 196608;
    cudaFuncSetAttribute(k_main, cudaFuncAttributeMaxDynamicSharedMemorySize, (int)smem);

    k_split<<<N / 8, 256>>>(X, C);
    k_main<<<dim3(NB, 2), 512, smem>>>(T);
    k_loss<<<1, 1024>>>(out);
}

// round 12
// speedup vs baseline: 1.1449x; 1.1002x over previous
#include <cuda_runtime.h>
#include <cuda_bf16.h>
#include <cstdint>

#define N       8192
#define D       128
#define BM      128
#define BN      128
#define NB      64
#define NK      33          // offsets 0..32 cover all pairs (circulant)
#define TOT     (NB * NK)   // 2112 tiles
#define GRIDX   148
#define P       16
#define MARGINF 1.0f
#define EPSF    1e-12f
#define FINF    __int_as_float(0x7f800000)
#define INFBITS 0x7f800000

// smem layout (dynamic, 192KB): A hi | A lo | B buf0 (hi|lo) | B buf1 (hi|lo)
#define SMA_HI  0u
#define SMA_LO  32768u
#define SMB0    65536u
#define SMB_SZ  65536u

// Scratch (no allocation allowed -> device globals)
__device__ float g_sq[N];
__device__ int   g_maxp[N];     // float bits, order-independent atomics
__device__ int   g_minn[N];
__device__ float g_dc[N];       // min distance to normalized centers
__device__ __nv_bfloat16 g_xhi[N * D];
__device__ __nv_bfloat16 g_xlo[N * D];

// ---------------------------------------------------------------------------
static __device__ __forceinline__ uint32_t smem_u32(const void* p) {
    uint32_t a;
    asm("{ .reg .u64 t; cvta.to.shared.u64 t, %1; cvt.u32.u64 %0, t; }" : "=r"(a) : "l"(p));
    return a;
}
static __device__ __forceinline__ void ldsm4(uint32_t* r, uint32_t addr) {
    asm volatile("ldmatrix.sync.aligned.m8n8.x4.shared.b16 {%0,%1,%2,%3}, [%4];"
                 : "=r"(r[0]), "=r"(r[1]), "=r"(r[2]), "=r"(r[3]) : "r"(addr));
}
static __device__ __forceinline__ void mma16816(float* c, const uint32_t* a,
                                                const uint32_t* b) {
    asm volatile("mma.sync.aligned.m16n8k16.row.col.f32.bf16.bf16.f32 "
                 "{%0,%1,%2,%3}, {%4,%5,%6,%7}, {%8,%9}, {%0,%1,%2,%3};"
                 : "+f"(c[0]), "+f"(c[1]), "+f"(c[2]), "+f"(c[3])
                 : "r"(a[0]), "r"(a[1]), "r"(a[2]), "r"(a[3]), "r"(b[0]), "r"(b[1]));
}
static __device__ __forceinline__ void cpa16(uint32_t dst, const void* src) {
    asm volatile("cp.async.cg.shared.global [%0], [%1], 16;" :: "r"(dst), "l"(src) : "memory");
}
#define CPA_COMMIT() asm volatile("cp.async.commit_group;" ::: "memory")
#define CPA_WAIT(n)  asm volatile("cp.async.wait_group %0;" :: "n"(n) : "memory")

// 128x128 bf16 tile -> smem, 256B rows, 16B-chunk xor swizzle (512 threads).
static __device__ __forceinline__ void cpa_tile(uint32_t dst_s,
                                                const __nv_bfloat16* src,
                                                int row0, int tid) {
    const char* base = (const char*)(src + (size_t)row0 * D);
    #pragma unroll
    for (int i = 0; i < 4; i++) {
        int idx = tid + i * 512;
        int r = idx >> 4, c = idx & 15;
        uint32_t off = (uint32_t)r * 256 + (uint32_t)((c ^ (r & 7)) << 4);
        cpa16(dst_s + off, base + (size_t)r * 256 + c * 16);
    }
}

// ---------------------------------------------------------------------------
// Fused prep: per block = 8 rows (warp each). Normalize centers into smem,
// split rows to bf16 hi/lo, squared norm, init mined arrays, dc = min center dist.
__global__ void k_split(const float* __restrict__ X, const float* __restrict__ C) {
    __shared__ float cn_s[P][D];
    const int tid = threadIdx.x, wid = tid >> 5, lane = tid & 31;

    #pragma unroll
    for (int cc = wid; cc < P; cc += 8) {
        float4 v = ((const float4*)(C + (size_t)cc * D))[lane];
        float s = v.x * v.x + v.y * v.y + v.z * v.z + v.w * v.w;
        #pragma unroll
        for (int o = 16; o; o >>= 1) s += __shfl_xor_sync(0xffffffffu, s, o);
        float inv = 1.0f / sqrtf(s);
        float* dst = &cn_s[cc][lane * 4];
        dst[0] = v.x * inv; dst[1] = v.y * inv; dst[2] = v.z * inv; dst[3] = v.w * inv;
    }

    const int w = blockIdx.x * 8 + wid;
    float4 v = ((const float4*)X)[(size_t)w * (D / 4) + lane];

    __nv_bfloat16 h0 = __float2bfloat16(v.x), h1 = __float2bfloat16(v.y);
    __nv_bfloat16 h2 = __float2bfloat16(v.z), h3 = __float2bfloat16(v.w);
    __nv_bfloat16 l0 = __float2bfloat16(v.x - __bfloat162float(h0));
    __nv_bfloat16 l1 = __float2bfloat16(v.y - __bfloat162float(h1));
    __nv_bfloat16 l2 = __float2bfloat16(v.z - __bfloat162float(h2));
    __nv_bfloat16 l3 = __float2bfloat16(v.w - __bfloat162float(h3));
    size_t o = (size_t)w * (D / 2) + lane * 2;
    ((__nv_bfloat162*)g_xhi)[o]     = __nv_bfloat162(h0, h1);
    ((__nv_bfloat162*)g_xhi)[o + 1] = __nv_bfloat162(h2, h3);
    ((__nv_bfloat162*)g_xlo)[o]     = __nv_bfloat162(l0, l1);
    ((__nv_bfloat162*)g_xlo)[o + 1] = __nv_bfloat162(l2, l3);

    float s = v.x * v.x + v.y * v.y + v.z * v.z + v.w * v.w;
    #pragma unroll
    for (int off = 16; off; off >>= 1) s += __shfl_xor_sync(0xffffffffu, s, off);

    __syncthreads();

    float dmin = FINF;
    #pragma unroll
    for (int p = 0; p < P; p++) {
        const float* cp = &cn_s[p][lane * 4];
        float dp = v.x * cp[0] + v.y * cp[1] + v.z * cp[2] + v.w * cp[3];
        #pragma unroll
        for (int off = 16; off; off >>= 1) dp += __shfl_xor_sync(0xffffffffu, dp, off);
        float d2 = fmaf(-2.0f, dp, s + 1.0f);
        float dcv = fmaxf(sqrtf(fmaxf(d2, 0.0f)), EPSF);
        dmin = fminf(dmin, dcv);
    }
    if (lane == 0) { g_sq[w] = s; g_maxp[w] = 0; g_minn[w] = INFBITS; g_dc[w] = dmin; }
}

// ---------------------------------------------------------------------------
// Persistent symmetric mining: 2112 (I,k) tiles split evenly over 148 blocks.
// 512 threads, 16 warps (4x4): warp tile 32 rows x 32 cols.
__global__ void __launch_bounds__(512, 1)
k_main(const int* __restrict__ T) {
    extern __shared__ __align__(1024) char smem[];
    __shared__ int   tCol[2][BN];
    __shared__ float sqCol[2][BN];

    const int tid  = threadIdx.x;
    const int lane = tid & 31;
    const int wid  = tid >> 5;
    const int mw   = wid & 3;
    const int nq   = wid >> 2;
    const int wm0  = mw * 32;
    const int wn0  = nq * 32;
    const uint32_t sb = smem_u32(smem);

    const int beg = (blockIdx.x * TOT) / GRIDX;
    const int end = ((blockIdx.x + 1) * TOT) / GRIDX;

    uint32_t a_rowoff[2], b_coloff[2];
    const uint32_t a_chk = (uint32_t)(lane >> 4);
    const uint32_t b_chk = (uint32_t)((lane >> 3) & 1);
    #pragma unroll
    for (int i = 0; i < 2; i++) {
        uint32_t r = wm0 + i * 16 + (lane & 7) + ((lane >> 3) & 1) * 8;
        a_rowoff[i] = (r * 256) | ((r & 7) << 28);
    }
    #pragma unroll
    for (int jj = 0; jj < 2; jj++) {
        uint32_t c = wn0 + jj * 16 + (lane & 7) + (lane >> 4) * 8;
        b_coloff[jj] = (c * 256) | ((c & 7) << 28);
    }

    int curI = beg / NK;
    float sqr[2][2]; int trow[2][2];
    #pragma unroll
    for (int i = 0; i < 2; i++)
        #pragma unroll
        for (int h = 0; h < 2; h++) {
            int gr = curI * BM + wm0 + i * 16 + h * 8 + (lane >> 2);
            sqr[i][h] = g_sq[gr];
            trow[i][h] = T[gr];
        }

    // Prologue: A(curI) + B(first J) + labels into buf 0, one group.
    cpa_tile(sb + SMA_HI, g_xhi, curI * BM, tid);
    cpa_tile(sb + SMA_LO, g_xlo, curI * BM, tid);
    {
        int J0 = (curI + (beg - curI * NK)) & (NB - 1);
        cpa_tile(sb + SMB0,          g_xhi, J0 * BN, tid);
        cpa_tile(sb + SMB0 + 32768u, g_xlo, J0 * BN, tid);
        if (tid < BN) { tCol[0][tid] = T[J0 * BN + tid]; sqCol[0][tid] = g_sq[J0 * BN + tid]; }
    }
    CPA_COMMIT();

    float mp[2][2], mn[2][2];
    #pragma unroll
    for (int i = 0; i < 2; i++)
        #pragma unroll
        for (int h = 0; h < 2; h++) { mp[i][h] = -1.0f; mn[i][h] = FINF; }

    for (int idx = beg; idx < end; idx++) {
        const int I = idx / NK;
        const int J = (I + (idx - I * NK)) & (NB - 1);
        const uint32_t buf = (uint32_t)((idx - beg) & 1);

        CPA_WAIT(0);
        __syncthreads();        // B(idx) resident; all warps done with prev iter

        if (I != curI) {
            // Flush row stats for curI (registers -> shfl -> atomics).
            #pragma unroll
            for (int i = 0; i < 2; i++)
                #pragma unroll
                for (int h = 0; h < 2; h++) {
                    float p = mp[i][h], q = mn[i][h];
                    #pragma unroll
                    for (int o = 1; o <= 2; o <<= 1) {
                        p = fmaxf(p, __shfl_xor_sync(0xffffffffu, p, o));
                        q = fminf(q, __shfl_xor_sync(0xffffffffu, q, o));
                    }
                    if ((lane & 3) == 0) {
                        int gr = curI * BM + wm0 + i * 16 + h * 8 + (lane >> 2);
                        atomicMax(&g_maxp[gr], __float_as_int(p));
                        atomicMin(&g_minn[gr], __float_as_int(q));
                    }
                    mp[i][h] = -1.0f; mn[i][h] = FINF;
                }
            curI = I;
            #pragma unroll
            for (int i = 0; i < 2; i++)
                #pragma unroll
                for (int h = 0; h < 2; h++) {
                    int gr = curI * BM + wm0 + i * 16 + h * 8 + (lane >> 2);
                    sqr[i][h] = g_sq[gr];
                    trow[i][h] = T[gr];
                }
            // Reload A (safe: all warps passed the sync above).
            cpa_tile(sb + SMA_HI, g_xhi, curI * BM, tid);
            cpa_tile(sb + SMA_LO, g_xlo, curI * BM, tid);
            CPA_COMMIT();
            if (idx + 1 < end) {
                int I1 = (idx + 1) / NK;
                int J1 = (I1 + (idx + 1 - I1 * NK)) & (NB - 1);
                cpa_tile(sb + SMB0 + (buf ^ 1) * SMB_SZ,          g_xhi, J1 * BN, tid);
                cpa_tile(sb + SMB0 + (buf ^ 1) * SMB_SZ + 32768u, g_xlo, J1 * BN, tid);
                CPA_COMMIT();
                if (tid < BN) {
                    tCol[buf ^ 1][tid] = T[J1 * BN + tid];
                    sqCol[buf ^ 1][tid] = g_sq[J1 * BN + tid];
                }
                CPA_WAIT(1);    // A resident, B(idx+1) may still fly
            } else {
                CPA_WAIT(0);
            }
            __syncthreads();
        } else if (idx + 1 < end) {
            int I1 = (idx + 1) / NK;
            int J1 = (I1 + (idx + 1 - I1 * NK)) & (NB - 1);
            cpa_tile(sb + SMB0 + (buf ^ 1) * SMB_SZ,          g_xhi, J1 * BN, tid);
            cpa_tile(sb + SMB0 + (buf ^ 1) * SMB_SZ + 32768u, g_xlo, J1 * BN, tid);
            CPA_COMMIT();
            if (tid < BN) {
                tCol[buf ^ 1][tid] = T[J1 * BN + tid];
                sqCol[buf ^ 1][tid] = g_sq[J1 * BN + tid];
            }
        }

        float acc[2][4][4];
        #pragma unroll
        for (int i = 0; i < 2; i++)
            #pragma unroll
            for (int j = 0; j < 4; j++)
                #pragma unroll
                for (int e = 0; e < 4; e++) acc[i][j][e] = 0.0f;

        const uint32_t ab_hi = sb + SMA_HI;
        const uint32_t ab_lo = sb + SMA_LO;
        const uint32_t bb_hi = sb + SMB0 + buf * SMB_SZ;
        const uint32_t bb_lo = bb_hi + 32768u;

        #pragma unroll
        for (int ks = 0; ks < 8; ks++) {
            uint32_t a_hi[2][4], a_lo[2][4], b_hi[2][4], b_lo[2][4];
            const uint32_t achunk = (uint32_t)(2 * ks) + a_chk;
            const uint32_t bchunk = (uint32_t)(2 * ks) + b_chk;
            #pragma unroll
            for (int i = 0; i < 2; i++) {
                uint32_t ro = a_rowoff[i];
                uint32_t off = (ro & 0x0FFFFFFFu) + ((achunk ^ (ro >> 28)) << 4);
                ldsm4(a_hi[i], ab_hi + off);
                ldsm4(a_lo[i], ab_lo + off);
            }
            #pragma unroll
            for (int jj = 0; jj < 2; jj++) {
                uint32_t co = b_coloff[jj];
                uint32_t off = (co & 0x0FFFFFFFu) + ((bchunk ^ (co >> 28)) << 4);
                ldsm4(b_hi[jj], bb_hi + off);
                ldsm4(b_lo[jj], bb_lo + off);
            }
            #pragma unroll
            for (int i = 0; i < 2; i++)
                #pragma unroll
                for (int jj = 0; jj < 2; jj++) {
                    mma16816(acc[i][2 * jj],     a_hi[i], &b_hi[jj][0]);
                    mma16816(acc[i][2 * jj + 1], a_hi[i], &b_hi[jj][2]);
                }
            #pragma unroll
            for (int i = 0; i < 2; i++)
                #pragma unroll
                for (int jj = 0; jj < 2; jj++) {
                    mma16816(acc[i][2 * jj],     a_hi[i], &b_lo[jj][0]);
                    mma16816(acc[i][2 * jj + 1], a_hi[i], &b_lo[jj][2]);
                }
            #pragma unroll
            for (int i = 0; i < 2; i++)
                #pragma unroll
                for (int jj = 0; jj < 2; jj++) {
                    mma16816(acc[i][2 * jj],     a_lo[i], &b_hi[jj][0]);
                    mma16816(acc[i][2 * jj + 1], a_lo[i], &b_hi[jj][2]);
                }
        }

        // Fused mining: row stats (registers) + col stats -> atomics.
        #pragma unroll
        for (int j = 0; j < 4; j++) {
            int cb = wn0 + j * 8 + (lane & 3) * 2;
            int tc0 = tCol[buf][cb], tc1 = tCol[buf][cb + 1];
            float sc0 = sqCol[buf][cb], sc1 = sqCol[buf][cb + 1];
            float cmax0 = -1.0f, cmax1 = -1.0f, cmin0 = FINF, cmin1 = FINF;
            #pragma unroll
            for (int i = 0; i < 2; i++)
                #pragma unroll
                for (int h = 0; h < 2; h++) {
                    float d0 = fmaxf(fmaf(-2.0f, acc[i][j][2 * h],     sqr[i][h] + sc0), 0.0f);
                    float d1 = fmaxf(fmaf(-2.0f, acc[i][j][2 * h + 1], sqr[i][h] + sc1), 0.0f);
                    if (trow[i][h] == tc0) { mp[i][h] = fmaxf(mp[i][h], d0);
                                             cmax0 = fmaxf(cmax0, d0); }
                    else                   { mn[i][h] = fminf(mn[i][h], d0);
                                             cmin0 = fminf(cmin0, d0); }
                    if (trow[i][h] == tc1) { mp[i][h] = fmaxf(mp[i][h], d1);
                                             cmax1 = fmaxf(cmax1, d1); }
                    else                   { mn[i][h] = fminf(mn[i][h], d1);
                                             cmin1 = fminf(cmin1, d1); }
                }
            #pragma unroll
            for (int o = 4; o <= 16; o <<= 1) {
                cmax0 = fmaxf(cmax0, __shfl_xor_sync(0xffffffffu, cmax0, o));
                cmin0 = fminf(cmin0, __shfl_xor_sync(0xffffffffu, cmin0, o));
                cmax1 = fmaxf(cmax1, __shfl_xor_sync(0xffffffffu, cmax1, o));
                cmin1 = fminf(cmin1, __shfl_xor_sync(0xffffffffu, cmin1, o));
            }
            if (lane < 4) {
                int gcol = J * BN + wn0 + j * 8 + lane * 2;
                atomicMax(&g_maxp[gcol], __float_as_int(cmax0));
                atomicMin(&g_minn[gcol], __float_as_int(cmin0));
                atomicMax(&g_maxp[gcol + 1], __float_as_int(cmax1));
                atomicMin(&g_minn[gcol + 1], __float_as_int(cmin1));
            }
        }
    }

    // Final row-stat flush for the last I.
    #pragma unroll
    for (int i = 0; i < 2; i++)
        #pragma unroll
        for (int h = 0; h < 2; h++) {
            float p = mp[i][h], q = mn[i][h];
            #pragma unroll
            for (int o = 1; o <= 2; o <<= 1) {
                p = fmaxf(p, __shfl_xor_sync(0xffffffffu, p, o));
                q = fminf(q, __shfl_xor_sync(0xffffffffu, q, o));
            }
            if ((lane & 3) == 0) {
                int gr = curI * BM + wm0 + i * 16 + h * 8 + (lane >> 2);
                atomicMax(&g_maxp[gr], __float_as_int(p));
                atomicMin(&g_minn[gr], __float_as_int(q));
            }
        }
}

// ---------------------------------------------------------------------------
// Final loss: one block, deterministic fixed-order accumulation + tree sum.
__global__ void k_loss(float* __restrict__ out) {
    __shared__ float sh[1024];
    const int t = threadIdx.x;
    float sum = 0.0f;
    #pragma unroll
    for (int k = 0; k < N / 1024; k++) {
        int r = t + k * 1024;
        float mpv = __int_as_float(g_maxp[r]);
        float mnv = __int_as_float(g_minn[r]);
        float dap = sqrtf(fmaxf(mpv, EPSF));
        float dan = isinf(mnv) ? (dap + MARGINF) : sqrtf(fmaxf(mnv, EPSF));
        dan = fminf(dan, g_dc[r]);
        sum += fmaxf(dap - dan + MARGINF, 0.0f);
    }
    sh[t] = sum;
    __syncthreads();
    for (int s = 512; s; s >>= 1) {
        if (t < s) sh[t] += sh[t + s];
        __syncthreads();
    }
    if (t == 0) out[0] = sh[0] / (float)N;
}

// ---------------------------------------------------------------------------
extern "C" void kernel_launch(void* const* d_in, const int* in_sizes, int n_in,
                              void* d_out, int out_size) {
    const float* X = (const float*)d_in[0];
    const int*   T = (const int*)d_in[1];
    const float* C = (const float*)d_in[2];
    float* out = (float*)d_out;

    size_t smem = 196608;
    cudaFuncSetAttribute(k_main, cudaFuncAttributeMaxDynamicSharedMemorySize, (int)smem);

    k_split<<<N / 8, 256>>>(X, C);
    k_main<<<GRIDX, 512, smem>>>(T);
    k_loss<<<1, 1024>>>(out);
}

// round 13
// speedup vs baseline: 1.3940x; 1.2176x over previous
#include <cuda_runtime.h>
#include <cuda_fp16.h>
#include <cstdint>

#define N       8192
#define D       128
#define BM      128
#define BN      128
#define NB      64
#define NK      33          // offsets 0..32 cover all pairs (circulant)
#define TOT     (NB * NK)   // 2112 tiles
#define GRIDX   148
#define P       16
#define MARGINF 1.0f
#define EPSF    1e-12f
#define FINF    __int_as_float(0x7f800000)
#define INFBITS 0x7f800000

// smem layout (dynamic, 160KB): A hi | B buf0 (hi|lo) | B buf1 (hi|lo)
#define SMA_HI  0u
#define SMB0    32768u
#define SMB_SZ  65536u
#define SMEM_TOTAL 163840

// Scratch (no allocation allowed -> device globals)
__device__ float g_sq[N];
__device__ int   g_maxp[N];     // float bits, order-independent atomics
__device__ int   g_minn[N];
__device__ float g_dc[N];       // min distance to normalized centers
__device__ __half g_xhi[N * D];
__device__ __half g_xlo[N * D];

// ---------------------------------------------------------------------------
static __device__ __forceinline__ uint32_t smem_u32(const void* p) {
    uint32_t a;
    asm("{ .reg .u64 t; cvta.to.shared.u64 t, %1; cvt.u32.u64 %0, t; }" : "=r"(a) : "l"(p));
    return a;
}
static __device__ __forceinline__ void ldsm4(uint32_t* r, uint32_t addr) {
    asm volatile("ldmatrix.sync.aligned.m8n8.x4.shared.b16 {%0,%1,%2,%3}, [%4];"
                 : "=r"(r[0]), "=r"(r[1]), "=r"(r[2]), "=r"(r[3]) : "r"(addr));
}
static __device__ __forceinline__ void mma16816(float* c, const uint32_t* a,
                                                const uint32_t* b) {
    asm volatile("mma.sync.aligned.m16n8k16.row.col.f32.f16.f16.f32 "
                 "{%0,%1,%2,%3}, {%4,%5,%6,%7}, {%8,%9}, {%0,%1,%2,%3};"
                 : "+f"(c[0]), "+f"(c[1]), "+f"(c[2]), "+f"(c[3])
                 : "r"(a[0]), "r"(a[1]), "r"(a[2]), "r"(a[3]), "r"(b[0]), "r"(b[1]));
}
static __device__ __forceinline__ void cpa16(uint32_t dst, const void* src) {
    asm volatile("cp.async.cg.shared.global [%0], [%1], 16;" :: "r"(dst), "l"(src) : "memory");
}
#define CPA_COMMIT() asm volatile("cp.async.commit_group;" ::: "memory")
#define CPA_WAIT(n)  asm volatile("cp.async.wait_group %0;" :: "n"(n) : "memory")

// 128x128 fp16 tile -> smem, 256B rows, 16B-chunk xor swizzle (512 threads).
static __device__ __forceinline__ void cpa_tile(uint32_t dst_s,
                                                const __half* src,
                                                int row0, int tid) {
    const char* base = (const char*)(src + (size_t)row0 * D);
    #pragma unroll
    for (int i = 0; i < 4; i++) {
        int idx = tid + i * 512;
        int r = idx >> 4, c = idx & 15;
        uint32_t off = (uint32_t)r * 256 + (uint32_t)((c ^ (r & 7)) << 4);
        cpa16(dst_s + off, base + (size_t)r * 256 + c * 16);
    }
}

// ---------------------------------------------------------------------------
// Fused prep: per block = 8 rows (warp each). Normalize centers into smem,
// split rows to fp16 hi/lo, squared norm, init mined arrays, dc = min center dist.
__global__ void k_split(const float* __restrict__ X, const float* __restrict__ C) {
    __shared__ float cn_s[P][D];
    const int tid = threadIdx.x, wid = tid >> 5, lane = tid & 31;

    #pragma unroll
    for (int cc = wid; cc < P; cc += 8) {
        float4 v = ((const float4*)(C + (size_t)cc * D))[lane];
        float s = v.x * v.x + v.y * v.y + v.z * v.z + v.w * v.w;
        #pragma unroll
        for (int o = 16; o; o >>= 1) s += __shfl_xor_sync(0xffffffffu, s, o);
        float inv = 1.0f / sqrtf(s);
        float* dst = &cn_s[cc][lane * 4];
        dst[0] = v.x * inv; dst[1] = v.y * inv; dst[2] = v.z * inv; dst[3] = v.w * inv;
    }

    const int w = blockIdx.x * 8 + wid;
    float4 v = ((const float4*)X)[(size_t)w * (D / 4) + lane];

    __half h0 = __float2half(v.x), h1 = __float2half(v.y);
    __half h2 = __float2half(v.z), h3 = __float2half(v.w);
    __half l0 = __float2half(v.x - __half2float(h0));
    __half l1 = __float2half(v.y - __half2float(h1));
    __half l2 = __float2half(v.z - __half2float(h2));
    __half l3 = __float2half(v.w - __half2float(h3));
    size_t o = (size_t)w * (D / 2) + lane * 2;
    ((__half2*)g_xhi)[o]     = __halves2half2(h0, h1);
    ((__half2*)g_xhi)[o + 1] = __halves2half2(h2, h3);
    ((__half2*)g_xlo)[o]     = __halves2half2(l0, l1);
    ((__half2*)g_xlo)[o + 1] = __halves2half2(l2, l3);

    float s = v.x * v.x + v.y * v.y + v.z * v.z + v.w * v.w;
    #pragma unroll
    for (int off = 16; off; off >>= 1) s += __shfl_xor_sync(0xffffffffu, s, off);

    __syncthreads();

    float dmin = FINF;
    #pragma unroll
    for (int p = 0; p < P; p++) {
        const float* cp = &cn_s[p][lane * 4];
        float dp = v.x * cp[0] + v.y * cp[1] + v.z * cp[2] + v.w * cp[3];
        #pragma unroll
        for (int off = 16; off; off >>= 1) dp += __shfl_xor_sync(0xffffffffu, dp, off);
        float d2 = fmaf(-2.0f, dp, s + 1.0f);
        float dcv = fmaxf(sqrtf(fmaxf(d2, 0.0f)), EPSF);
        dmin = fminf(dmin, dcv);
    }
    if (lane == 0) { g_sq[w] = s; g_maxp[w] = 0; g_minn[w] = INFBITS; g_dc[w] = dmin; }
}

// ---------------------------------------------------------------------------
// Persistent symmetric mining: 2112 (I,k) tiles split evenly over 148 blocks.
// 512 threads, 16 warps (4x4): warp tile 32 rows x 32 cols.
// fp16 2-pass: dot ~= a_hi*(b_hi + b_lo); A-lo never needed.
__global__ void __launch_bounds__(512, 1)
k_main(const int* __restrict__ T) {
    extern __shared__ __align__(1024) char smem[];
    __shared__ int   tCol[2][BN];
    __shared__ float sqCol[2][BN];

    const int tid  = threadIdx.x;
    const int lane = tid & 31;
    const int wid  = tid >> 5;
    const int mw   = wid & 3;
    const int nq   = wid >> 2;
    const int wm0  = mw * 32;
    const int wn0  = nq * 32;
    const uint32_t sb = smem_u32(smem);

    const int beg = (blockIdx.x * TOT) / GRIDX;
    const int end = ((blockIdx.x + 1) * TOT) / GRIDX;

    uint32_t a_rowoff[2], b_coloff[2];
    const uint32_t a_chk = (uint32_t)(lane >> 4);
    const uint32_t b_chk = (uint32_t)((lane >> 3) & 1);
    #pragma unroll
    for (int i = 0; i < 2; i++) {
        uint32_t r = wm0 + i * 16 + (lane & 7) + ((lane >> 3) & 1) * 8;
        a_rowoff[i] = (r * 256) | ((r & 7) << 28);
    }
    #pragma unroll
    for (int jj = 0; jj < 2; jj++) {
        uint32_t c = wn0 + jj * 16 + (lane & 7) + (lane >> 4) * 8;
        b_coloff[jj] = (c * 256) | ((c & 7) << 28);
    }

    int curI = beg / NK;
    float sqr[2][2]; int trow[2][2];
    #pragma unroll
    for (int i = 0; i < 2; i++)
        #pragma unroll
        for (int h = 0; h < 2; h++) {
            int gr = curI * BM + wm0 + i * 16 + h * 8 + (lane >> 2);
            sqr[i][h] = g_sq[gr];
            trow[i][h] = T[gr];
        }

    // Prologue: A(curI) hi + B(first J) hi/lo + labels into buf 0.
    cpa_tile(sb + SMA_HI, g_xhi, curI * BM, tid);
    {
        int J0 = (curI + (beg - curI * NK)) & (NB - 1);
        cpa_tile(sb + SMB0,          g_xhi, J0 * BN, tid);
        cpa_tile(sb + SMB0 + 32768u, g_xlo, J0 * BN, tid);
        if (tid < BN) { tCol[0][tid] = T[J0 * BN + tid]; sqCol[0][tid] = g_sq[J0 * BN + tid]; }
    }
    CPA_COMMIT();

    float mp[2][2], mn[2][2];
    #pragma unroll
    for (int i = 0; i < 2; i++)
        #pragma unroll
        for (int h = 0; h < 2; h++) { mp[i][h] = -1.0f; mn[i][h] = FINF; }

    for (int idx = beg; idx < end; idx++) {
        const int I = idx / NK;
        const int J = (I + (idx - I * NK)) & (NB - 1);
        const uint32_t buf = (uint32_t)((idx - beg) & 1);

        CPA_WAIT(0);
        __syncthreads();        // B(idx) resident; all warps done with prev iter

        if (I != curI) {
            // Flush row stats for curI (registers -> shfl -> atomics).
            #pragma unroll
            for (int i = 0; i < 2; i++)
                #pragma unroll
                for (int h = 0; h < 2; h++) {
                    float p = mp[i][h], q = mn[i][h];
                    #pragma unroll
                    for (int o = 1; o <= 2; o <<= 1) {
                        p = fmaxf(p, __shfl_xor_sync(0xffffffffu, p, o));
                        q = fminf(q, __shfl_xor_sync(0xffffffffu, q, o));
                    }
                    if ((lane & 3) == 0) {
                        int gr = curI * BM + wm0 + i * 16 + h * 8 + (lane >> 2);
                        atomicMax(&g_maxp[gr], __float_as_int(p));
                        atomicMin(&g_minn[gr], __float_as_int(q));
                    }
                    mp[i][h] = -1.0f; mn[i][h] = FINF;
                }
            curI = I;
            #pragma unroll
            for (int i = 0; i < 2; i++)
                #pragma unroll
                for (int h = 0; h < 2; h++) {
                    int gr = curI * BM + wm0 + i * 16 + h * 8 + (lane >> 2);
                    sqr[i][h] = g_sq[gr];
                    trow[i][h] = T[gr];
                }
            // Reload A hi (safe: all warps passed the sync above).
            cpa_tile(sb + SMA_HI, g_xhi, curI * BM, tid);
            CPA_COMMIT();
            if (idx + 1 < end) {
                int I1 = (idx + 1) / NK;
                int J1 = (I1 + (idx + 1 - I1 * NK)) & (NB - 1);
                cpa_tile(sb + SMB0 + (buf ^ 1) * SMB_SZ,          g_xhi, J1 * BN, tid);
                cpa_tile(sb + SMB0 + (buf ^ 1) * SMB_SZ + 32768u, g_xlo, J1 * BN, tid);
                CPA_COMMIT();
                if (tid < BN) {
                    tCol[buf ^ 1][tid] = T[J1 * BN + tid];
                    sqCol[buf ^ 1][tid] = g_sq[J1 * BN + tid];
                }
                CPA_WAIT(1);    // A resident, B(idx+1) may still fly
            } else {
                CPA_WAIT(0);
            }
            __syncthreads();
        } else if (idx + 1 < end) {
            int I1 = (idx + 1) / NK;
            int J1 = (I1 + (idx + 1 - I1 * NK)) & (NB - 1);
            cpa_tile(sb + SMB0 + (buf ^ 1) * SMB_SZ,          g_xhi, J1 * BN, tid);
            cpa_tile(sb + SMB0 + (buf ^ 1) * SMB_SZ + 32768u, g_xlo, J1 * BN, tid);
            CPA_COMMIT();
            if (tid < BN) {
                tCol[buf ^ 1][tid] = T[J1 * BN + tid];
                sqCol[buf ^ 1][tid] = g_sq[J1 * BN + tid];
            }
        }

        float acc[2][4][4];
        #pragma unroll
        for (int i = 0; i < 2; i++)
            #pragma unroll
            for (int j = 0; j < 4; j++)
                #pragma unroll
                for (int e = 0; e < 4; e++) acc[i][j][e] = 0.0f;

        const uint32_t ab_hi = sb + SMA_HI;
        const uint32_t bb_hi = sb + SMB0 + buf * SMB_SZ;
        const uint32_t bb_lo = bb_hi + 32768u;

        #pragma unroll
        for (int ks = 0; ks < 8; ks++) {
            uint32_t a_hi[2][4], b_hi[2][4], b_lo[2][4];
            const uint32_t achunk = (uint32_t)(2 * ks) + a_chk;
            const uint32_t bchunk = (uint32_t)(2 * ks) + b_chk;
            #pragma unroll
            for (int i = 0; i < 2; i++) {
                uint32_t ro = a_rowoff[i];
                uint32_t off = (ro & 0x0FFFFFFFu) + ((achunk ^ (ro >> 28)) << 4);
                ldsm4(a_hi[i], ab_hi + off);
            }
            #pragma unroll
            for (int jj = 0; jj < 2; jj++) {
                uint32_t co = b_coloff[jj];
                uint32_t off = (co & 0x0FFFFFFFu) + ((bchunk ^ (co >> 28)) << 4);
                ldsm4(b_hi[jj], bb_hi + off);
                ldsm4(b_lo[jj], bb_lo + off);
            }
            // Two passes: a_hi*b_hi + a_hi*b_lo (same-acc writes spaced 8 apart).
            #pragma unroll
            for (int i = 0; i < 2; i++)
                #pragma unroll
                for (int jj = 0; jj < 2; jj++) {
                    mma16816(acc[i][2 * jj],     a_hi[i], &b_hi[jj][0]);
                    mma16816(acc[i][2 * jj + 1], a_hi[i], &b_hi[jj][2]);
                }
            #pragma unroll
            for (int i = 0; i < 2; i++)
                #pragma unroll
                for (int jj = 0; jj < 2; jj++) {
                    mma16816(acc[i][2 * jj],     a_hi[i], &b_lo[jj][0]);
                    mma16816(acc[i][2 * jj + 1], a_hi[i], &b_lo[jj][2]);
                }
        }

        // Fused mining: row stats (registers) + col stats -> atomics.
        #pragma unroll
        for (int j = 0; j < 4; j++) {
            int cb = wn0 + j * 8 + (lane & 3) * 2;
            int tc0 = tCol[buf][cb], tc1 = tCol[buf][cb + 1];
            float sc0 = sqCol[buf][cb], sc1 = sqCol[buf][cb + 1];
            float cmax0 = -1.0f, cmax1 = -1.0f, cmin0 = FINF, cmin1 = FINF;
            #pragma unroll
            for (int i = 0; i < 2; i++)
                #pragma unroll
                for (int h = 0; h < 2; h++) {
                    float d0 = fmaxf(fmaf(-2.0f, acc[i][j][2 * h],     sqr[i][h] + sc0), 0.0f);
                    float d1 = fmaxf(fmaf(-2.0f, acc[i][j][2 * h + 1], sqr[i][h] + sc1), 0.0f);
                    if (trow[i][h] == tc0) { mp[i][h] = fmaxf(mp[i][h], d0);
                                             cmax0 = fmaxf(cmax0, d0); }
                    else                   { mn[i][h] = fminf(mn[i][h], d0);
                                             cmin0 = fminf(cmin0, d0); }
                    if (trow[i][h] == tc1) { mp[i][h] = fmaxf(mp[i][h], d1);
                                             cmax1 = fmaxf(cmax1, d1); }
                    else                   { mn[i][h] = fminf(mn[i][h], d1);
                                             cmin1 = fminf(cmin1, d1); }
                }
            #pragma unroll
            for (int o = 4; o <= 16; o <<= 1) {
                cmax0 = fmaxf(cmax0, __shfl_xor_sync(0xffffffffu, cmax0, o));
                cmin0 = fminf(cmin0, __shfl_xor_sync(0xffffffffu, cmin0, o));
                cmax1 = fmaxf(cmax1, __shfl_xor_sync(0xffffffffu, cmax1, o));
                cmin1 = fminf(cmin1, __shfl_xor_sync(0xffffffffu, cmin1, o));
            }
            if (lane < 4) {
                int gcol = J * BN + wn0 + j * 8 + lane * 2;
                atomicMax(&g_maxp[gcol], __float_as_int(cmax0));
                atomicMin(&g_minn[gcol], __float_as_int(cmin0));
                atomicMax(&g_maxp[gcol + 1], __float_as_int(cmax1));
                atomicMin(&g_minn[gcol + 1], __float_as_int(cmin1));
            }
        }
    }

    // Final row-stat flush for the last I.
    #pragma unroll
    for (int i = 0; i < 2; i++)
        #pragma unroll
        for (int h = 0; h < 2; h++) {
            float p = mp[i][h], q = mn[i][h];
            #pragma unroll
            for (int o = 1; o <= 2; o <<= 1) {
                p = fmaxf(p, __shfl_xor_sync(0xffffffffu, p, o));
                q = fminf(q, __shfl_xor_sync(0xffffffffu, q, o));
            }
            if ((lane & 3) == 0) {
                int gr = curI * BM + wm0 + i * 16 + h * 8 + (lane >> 2);
                atomicMax(&g_maxp[gr], __float_as_int(p));
                atomicMin(&g_minn[gr], __float_as_int(q));
            }
        }
}

// ---------------------------------------------------------------------------
// Final loss: one block, deterministic fixed-order accumulation + tree sum.
__global__ void k_loss(float* __restrict__ out) {
    __shared__ float sh[1024];
    const int t = threadIdx.x;
    float sum = 0.0f;
    #pragma unroll
    for (int k = 0; k < N / 1024; k++) {
        int r = t + k * 1024;
        float mpv = __int_as_float(g_maxp[r]);
        float mnv = __int_as_float(g_minn[r]);
        float dap = sqrtf(fmaxf(mpv, EPSF));
        float dan = isinf(mnv) ? (dap + MARGINF) : sqrtf(fmaxf(mnv, EPSF));
        dan = fminf(dan, g_dc[r]);
        sum += fmaxf(dap - dan + MARGINF, 0.0f);
    }
    sh[t] = sum;
    __syncthreads();
    for (int s = 512; s; s >>= 1) {
        if (t < s) sh[t] += sh[t + s];
        __syncthreads();
    }
    if (t == 0) out[0] = sh[0] / (float)N;
}

// ---------------------------------------------------------------------------
extern "C" void kernel_launch(void* const* d_in, const int* in_sizes, int n_in,
                              void* d_out, int out_size) {
    const float* X = (const float*)d_in[0];
    const int*   T = (const int*)d_in[1];
    const float* C = (const float*)d_in[2];
    float* out = (float*)d_out;

    cudaFuncSetAttribute(k_main, cudaFuncAttributeMaxDynamicSharedMemorySize, SMEM_TOTAL);

    k_split<<<N / 8, 256>>>(X, C);
    k_main<<<GRIDX, 512, SMEM_TOTAL>>>(T);
    k_loss<<<1, 1024>>>(out);
}

// round 14
// speedup vs baseline: 1.7644x; 1.2657x over previous
#include <cuda_runtime.h>
#include <cuda_fp16.h>
#include <cstdint>

#define N       8192
#define D       128
#define BM      128
#define BN      128
#define NB      64
#define NK      33          // offsets 0..32 cover all pairs (circulant)
#define TOT     (NB * NK)   // 2112 tiles
#define GRIDX   148
#define P       16
#define MARGINF 1.0f
#define EPSF    1e-12f
#define FINF    __int_as_float(0x7f800000)
#define INFBITS 0x7f800000

// smem layout (dynamic, 96KB): A | B buf0 | B buf1
#define SMA     0u
#define SMB0    32768u
#define SMB_SZ  32768u
#define SMEM_TOTAL 98304

// Scratch (no allocation allowed -> device globals)
__device__ float g_sq[N];
__device__ int   g_maxp[N];     // float bits, order-independent atomics
__device__ int   g_minn[N];
__device__ float g_dc[N];       // min distance to normalized centers
__device__ __half g_xh[N * D];

// ---------------------------------------------------------------------------
static __device__ __forceinline__ uint32_t smem_u32(const void* p) {
    uint32_t a;
    asm("{ .reg .u64 t; cvta.to.shared.u64 t, %1; cvt.u32.u64 %0, t; }" : "=r"(a) : "l"(p));
    return a;
}
static __device__ __forceinline__ void ldsm4(uint32_t* r, uint32_t addr) {
    asm volatile("ldmatrix.sync.aligned.m8n8.x4.shared.b16 {%0,%1,%2,%3}, [%4];"
                 : "=r"(r[0]), "=r"(r[1]), "=r"(r[2]), "=r"(r[3]) : "r"(addr));
}
static __device__ __forceinline__ void mma16816(float* c, const uint32_t* a,
                                                const uint32_t* b) {
    asm volatile("mma.sync.aligned.m16n8k16.row.col.f32.f16.f16.f32 "
                 "{%0,%1,%2,%3}, {%4,%5,%6,%7}, {%8,%9}, {%0,%1,%2,%3};"
                 : "+f"(c[0]), "+f"(c[1]), "+f"(c[2]), "+f"(c[3])
                 : "r"(a[0]), "r"(a[1]), "r"(a[2]), "r"(a[3]), "r"(b[0]), "r"(b[1]));
}
static __device__ __forceinline__ void cpa16(uint32_t dst, const void* src) {
    asm volatile("cp.async.cg.shared.global [%0], [%1], 16;" :: "r"(dst), "l"(src) : "memory");
}
#define CPA_COMMIT() asm volatile("cp.async.commit_group;" ::: "memory")
#define CPA_WAIT(n)  asm volatile("cp.async.wait_group %0;" :: "n"(n) : "memory")

// 128x128 fp16 tile -> smem, 256B rows, 16B-chunk xor swizzle (512 threads).
static __device__ __forceinline__ void cpa_tile(uint32_t dst_s,
                                                const __half* src,
                                                int row0, int tid) {
    const char* base = (const char*)(src + (size_t)row0 * D);
    #pragma unroll
    for (int i = 0; i < 4; i++) {
        int idx = tid + i * 512;
        int r = idx >> 4, c = idx & 15;
        uint32_t off = (uint32_t)r * 256 + (uint32_t)((c ^ (r & 7)) << 4);
        cpa16(dst_s + off, base + (size_t)r * 256 + c * 16);
    }
}

// ---------------------------------------------------------------------------
// Fused prep: per block = 8 rows (warp each). Normalize centers into smem,
// round rows to fp16, squared norm, init mined arrays, dc = min center dist.
__global__ void k_split(const float* __restrict__ X, const float* __restrict__ C) {
    __shared__ float cn_s[P][D];
    const int tid = threadIdx.x, wid = tid >> 5, lane = tid & 31;

    #pragma unroll
    for (int cc = wid; cc < P; cc += 8) {
        float4 v = ((const float4*)(C + (size_t)cc * D))[lane];
        float s = v.x * v.x + v.y * v.y + v.z * v.z + v.w * v.w;
        #pragma unroll
        for (int o = 16; o; o >>= 1) s += __shfl_xor_sync(0xffffffffu, s, o);
        float inv = 1.0f / sqrtf(s);
        float* dst = &cn_s[cc][lane * 4];
        dst[0] = v.x * inv; dst[1] = v.y * inv; dst[2] = v.z * inv; dst[3] = v.w * inv;
    }

    const int w = blockIdx.x * 8 + wid;
    float4 v = ((const float4*)X)[(size_t)w * (D / 4) + lane];

    __half h0 = __float2half(v.x), h1 = __float2half(v.y);
    __half h2 = __float2half(v.z), h3 = __float2half(v.w);
    size_t o = (size_t)w * (D / 2) + lane * 2;
    ((__half2*)g_xh)[o]     = __halves2half2(h0, h1);
    ((__half2*)g_xh)[o + 1] = __halves2half2(h2, h3);

    float s = v.x * v.x + v.y * v.y + v.z * v.z + v.w * v.w;
    #pragma unroll
    for (int off = 16; off; off >>= 1) s += __shfl_xor_sync(0xffffffffu, s, off);

    __syncthreads();

    float dmin = FINF;
    #pragma unroll
    for (int p = 0; p < P; p++) {
        const float* cp = &cn_s[p][lane * 4];
        float dp = v.x * cp[0] + v.y * cp[1] + v.z * cp[2] + v.w * cp[3];
        #pragma unroll
        for (int off = 16; off; off >>= 1) dp += __shfl_xor_sync(0xffffffffu, dp, off);
        float d2 = fmaf(-2.0f, dp, s + 1.0f);
        float dcv = fmaxf(sqrtf(fmaxf(d2, 0.0f)), EPSF);
        dmin = fminf(dmin, dcv);
    }
    if (lane == 0) { g_sq[w] = s; g_maxp[w] = 0; g_minn[w] = INFBITS; g_dc[w] = dmin; }
}

// ---------------------------------------------------------------------------
// Persistent symmetric mining: 2112 (I,k) tiles split evenly over 148 blocks.
// 512 threads, 16 warps (4x4): warp tile 32 rows x 32 cols. Pure fp16 1-pass.
__global__ void __launch_bounds__(512, 1)
k_main(const int* __restrict__ T) {
    extern __shared__ __align__(1024) char smem[];
    __shared__ int   tCol[2][BN];
    __shared__ float sqCol[2][BN];

    const int tid  = threadIdx.x;
    const int lane = tid & 31;
    const int wid  = tid >> 5;
    const int mw   = wid & 3;
    const int nq   = wid >> 2;
    const int wm0  = mw * 32;
    const int wn0  = nq * 32;
    const uint32_t sb = smem_u32(smem);

    const int beg = (blockIdx.x * TOT) / GRIDX;
    const int end = ((blockIdx.x + 1) * TOT) / GRIDX;

    uint32_t a_rowoff[2], b_coloff[2];
    const uint32_t a_chk = (uint32_t)(lane >> 4);
    const uint32_t b_chk = (uint32_t)((lane >> 3) & 1);
    #pragma unroll
    for (int i = 0; i < 2; i++) {
        uint32_t r = wm0 + i * 16 + (lane & 7) + ((lane >> 3) & 1) * 8;
        a_rowoff[i] = (r * 256) | ((r & 7) << 28);
    }
    #pragma unroll
    for (int jj = 0; jj < 2; jj++) {
        uint32_t c = wn0 + jj * 16 + (lane & 7) + (lane >> 4) * 8;
        b_coloff[jj] = (c * 256) | ((c & 7) << 28);
    }

    int curI = beg / NK;
    float sqr[2][2]; int trow[2][2];
    #pragma unroll
    for (int i = 0; i < 2; i++)
        #pragma unroll
        for (int h = 0; h < 2; h++) {
            int gr = curI * BM + wm0 + i * 16 + h * 8 + (lane >> 2);
            sqr[i][h] = g_sq[gr];
            trow[i][h] = T[gr];
        }

    // Prologue: A(curI) + B(first J) + labels into buf 0.
    cpa_tile(sb + SMA, g_xh, curI * BM, tid);
    {
        int J0 = (curI + (beg - curI * NK)) & (NB - 1);
        cpa_tile(sb + SMB0, g_xh, J0 * BN, tid);
        if (tid < BN) { tCol[0][tid] = T[J0 * BN + tid]; sqCol[0][tid] = g_sq[J0 * BN + tid]; }
    }
    CPA_COMMIT();

    float mp[2][2], mn[2][2];
    #pragma unroll
    for (int i = 0; i < 2; i++)
        #pragma unroll
        for (int h = 0; h < 2; h++) { mp[i][h] = -1.0f; mn[i][h] = FINF; }

    for (int idx = beg; idx < end; idx++) {
        const int I = idx / NK;
        const int J = (I + (idx - I * NK)) & (NB - 1);
        const uint32_t buf = (uint32_t)((idx - beg) & 1);

        CPA_WAIT(0);
        __syncthreads();        // B(idx) resident; all warps done with prev iter

        if (I != curI) {
            // Flush row stats for curI.
            #pragma unroll
            for (int i = 0; i < 2; i++)
                #pragma unroll
                for (int h = 0; h < 2; h++) {
                    float p = mp[i][h], q = mn[i][h];
                    #pragma unroll
                    for (int o = 1; o <= 2; o <<= 1) {
                        p = fmaxf(p, __shfl_xor_sync(0xffffffffu, p, o));
                        q = fminf(q, __shfl_xor_sync(0xffffffffu, q, o));
                    }
                    if ((lane & 3) == 0) {
                        int gr = curI * BM + wm0 + i * 16 + h * 8 + (lane >> 2);
                        atomicMax(&g_maxp[gr], __float_as_int(p));
                        atomicMin(&g_minn[gr], __float_as_int(q));
                    }
                    mp[i][h] = -1.0f; mn[i][h] = FINF;
                }
            curI = I;
            #pragma unroll
            for (int i = 0; i < 2; i++)
                #pragma unroll
                for (int h = 0; h < 2; h++) {
                    int gr = curI * BM + wm0 + i * 16 + h * 8 + (lane >> 2);
                    sqr[i][h] = g_sq[gr];
                    trow[i][h] = T[gr];
                }
            // Reload A (safe: all warps passed the sync above).
            cpa_tile(sb + SMA, g_xh, curI * BM, tid);
            CPA_COMMIT();
            if (idx + 1 < end) {
                int I1 = (idx + 1) / NK;
                int J1 = (I1 + (idx + 1 - I1 * NK)) & (NB - 1);
                cpa_tile(sb + SMB0 + (buf ^ 1) * SMB_SZ, g_xh, J1 * BN, tid);
                CPA_COMMIT();
                if (tid < BN) {
                    tCol[buf ^ 1][tid] = T[J1 * BN + tid];
                    sqCol[buf ^ 1][tid] = g_sq[J1 * BN + tid];
                }
                CPA_WAIT(1);    // A resident, B(idx+1) may still fly
            } else {
                CPA_WAIT(0);
            }
            __syncthreads();
        } else if (idx + 1 < end) {
            int I1 = (idx + 1) / NK;
            int J1 = (I1 + (idx + 1 - I1 * NK)) & (NB - 1);
            cpa_tile(sb + SMB0 + (buf ^ 1) * SMB_SZ, g_xh, J1 * BN, tid);
            CPA_COMMIT();
            if (tid < BN) {
                tCol[buf ^ 1][tid] = T[J1 * BN + tid];
                sqCol[buf ^ 1][tid] = g_sq[J1 * BN + tid];
            }
        }

        float acc[2][4][4];
        #pragma unroll
        for (int i = 0; i < 2; i++)
            #pragma unroll
            for (int j = 0; j < 4; j++)
                #pragma unroll
                for (int e = 0; e < 4; e++) acc[i][j][e] = 0.0f;

        const uint32_t ab = sb + SMA;
        const uint32_t bb = sb + SMB0 + buf * SMB_SZ;

        #pragma unroll
        for (int ks = 0; ks < 8; ks++) {
            uint32_t a_f[2][4], b_f[2][4];
            const uint32_t achunk = (uint32_t)(2 * ks) + a_chk;
            const uint32_t bchunk = (uint32_t)(2 * ks) + b_chk;
            #pragma unroll
            for (int i = 0; i < 2; i++) {
                uint32_t ro = a_rowoff[i];
                uint32_t off = (ro & 0x0FFFFFFFu) + ((achunk ^ (ro >> 28)) << 4);
                ldsm4(a_f[i], ab + off);
            }
            #pragma unroll
            for (int jj = 0; jj < 2; jj++) {
                uint32_t co = b_coloff[jj];
                uint32_t off = (co & 0x0FFFFFFFu) + ((bchunk ^ (co >> 28)) << 4);
                ldsm4(b_f[jj], bb + off);
            }
            #pragma unroll
            for (int i = 0; i < 2; i++)
                #pragma unroll
                for (int jj = 0; jj < 2; jj++) {
                    mma16816(acc[i][2 * jj],     a_f[i], &b_f[jj][0]);
                    mma16816(acc[i][2 * jj + 1], a_f[i], &b_f[jj][2]);
                }
        }

        // Fused mining: row stats (registers) + col stats -> atomics.
        #pragma unroll
        for (int j = 0; j < 4; j++) {
            int cb = wn0 + j * 8 + (lane & 3) * 2;
            int tc0 = tCol[buf][cb], tc1 = tCol[buf][cb + 1];
            float sc0 = sqCol[buf][cb], sc1 = sqCol[buf][cb + 1];
            float cmax0 = -1.0f, cmax1 = -1.0f, cmin0 = FINF, cmin1 = FINF;
            #pragma unroll
            for (int i = 0; i < 2; i++)
                #pragma unroll
                for (int h = 0; h < 2; h++) {
                    float d0 = fmaxf(fmaf(-2.0f, acc[i][j][2 * h],     sqr[i][h] + sc0), 0.0f);
                    float d1 = fmaxf(fmaf(-2.0f, acc[i][j][2 * h + 1], sqr[i][h] + sc1), 0.0f);
                    if (trow[i][h] == tc0) { mp[i][h] = fmaxf(mp[i][h], d0);
                                             cmax0 = fmaxf(cmax0, d0); }
                    else                   { mn[i][h] = fminf(mn[i][h], d0);
                                             cmin0 = fminf(cmin0, d0); }
                    if (trow[i][h] == tc1) { mp[i][h] = fmaxf(mp[i][h], d1);
                                             cmax1 = fmaxf(cmax1, d1); }
                    else                   { mn[i][h] = fminf(mn[i][h], d1);
                                             cmin1 = fminf(cmin1, d1); }
                }
            #pragma unroll
            for (int o = 4; o <= 16; o <<= 1) {
                cmax0 = fmaxf(cmax0, __shfl_xor_sync(0xffffffffu, cmax0, o));
                cmin0 = fminf(cmin0, __shfl_xor_sync(0xffffffffu, cmin0, o));
                cmax1 = fmaxf(cmax1, __shfl_xor_sync(0xffffffffu, cmax1, o));
                cmin1 = fminf(cmin1, __shfl_xor_sync(0xffffffffu, cmin1, o));
            }
            if (lane < 4) {
                int gcol = J * BN + wn0 + j * 8 + lane * 2;
                atomicMax(&g_maxp[gcol], __float_as_int(cmax0));
                atomicMin(&g_minn[gcol], __float_as_int(cmin0));
                atomicMax(&g_maxp[gcol + 1], __float_as_int(cmax1));
                atomicMin(&g_minn[gcol + 1], __float_as_int(cmin1));
            }
        }
    }

    // Final row-stat flush for the last I.
    #pragma unroll
    for (int i = 0; i < 2; i++)
        #pragma unroll
        for (int h = 0; h < 2; h++) {
            float p = mp[i][h], q = mn[i][h];
            #pragma unroll
            for (int o = 1; o <= 2; o <<= 1) {
                p = fmaxf(p, __shfl_xor_sync(0xffffffffu, p, o));
                q = fminf(q, __shfl_xor_sync(0xffffffffu, q, o));
            }
            if ((lane & 3) == 0) {
                int gr = curI * BM + wm0 + i * 16 + h * 8 + (lane >> 2);
                atomicMax(&g_maxp[gr], __float_as_int(p));
                atomicMin(&g_minn[gr], __float_as_int(q));
            }
        }
}

// ---------------------------------------------------------------------------
// Final loss: one block, deterministic fixed-order accumulation + tree sum.
__global__ void k_loss(float* __restrict__ out) {
    __shared__ float sh[1024];
    const int t = threadIdx.x;
    float sum = 0.0f;
    #pragma unroll
    for (int k = 0; k < N / 1024; k++) {
        int r = t + k * 1024;
        float mpv = __int_as_float(g_maxp[r]);
        float mnv = __int_as_float(g_minn[r]);
        float dap = sqrtf(fmaxf(mpv, EPSF));
        float dan = isinf(mnv) ? (dap + MARGINF) : sqrtf(fmaxf(mnv, EPSF));
        dan = fminf(dan, g_dc[r]);
        sum += fmaxf(dap - dan + MARGINF, 0.0f);
    }
    sh[t] = sum;
    __syncthreads();
    for (int s = 512; s; s >>= 1) {
        if (t < s) sh[t] += sh[t + s];
        __syncthreads();
    }
    if (t == 0) out[0] = sh[0] / (float)N;
}

// ---------------------------------------------------------------------------
extern "C" void kernel_launch(void* const* d_in, const int* in_sizes, int n_in,
                              void* d_out, int out_size) {
    const float* X = (const float*)d_in[0];
    const int*   T = (const int*)d_in[1];
    const float* C = (const float*)d_in[2];
    float* out = (float*)d_out;

    cudaFuncSetAttribute(k_main, cudaFuncAttributeMaxDynamicSharedMemorySize, SMEM_TOTAL);

    k_split<<<N / 8, 256>>>(X, C);
    k_main<<<GRIDX, 512, SMEM_TOTAL>>>(T);
    k_loss<<<1, 1024>>>(out);
}

// round 15
// speedup vs baseline: 1.7797x; 1.0087x over previous
#include <cuda_runtime.h>
#include <cuda_fp16.h>
#include <cstdint>

#define N       8192
#define D       128
#define BM      128
#define BN      128
#define NB      64
#define NK      33          // offsets 0..32 cover all pairs (circulant)
#define TOT     (NB * NK)   // 2112 tiles
#define GRIDX   148
#define P       16
#define MARGINF 1.0f
#define EPSF    1e-12f
#define FINF    __int_as_float(0x7f800000)
#define INFBITS 0x7f800000

// smem layout (dynamic, 96KB): A | B buf0 | B buf1
#define SMA     0u
#define SMB0    32768u
#define SMB_SZ  32768u
#define SMEM_TOTAL 98304

// Scratch (no allocation allowed -> device globals)
__device__ float g_sq[N];
__device__ int   g_maxp[N];     // float bits, order-independent atomics
__device__ int   g_minn[N];
__device__ float g_dc[N];       // min distance to normalized centers
__device__ __half g_xh[N * D];

// ---------------------------------------------------------------------------
static __device__ __forceinline__ uint32_t smem_u32(const void* p) {
    uint32_t a;
    asm("{ .reg .u64 t; cvta.to.shared.u64 t, %1; cvt.u32.u64 %0, t; }" : "=r"(a) : "l"(p));
    return a;
}
static __device__ __forceinline__ void ldsm4(uint32_t* r, uint32_t addr) {
    asm volatile("ldmatrix.sync.aligned.m8n8.x4.shared.b16 {%0,%1,%2,%3}, [%4];"
                 : "=r"(r[0]), "=r"(r[1]), "=r"(r[2]), "=r"(r[3]) : "r"(addr));
}
static __device__ __forceinline__ void mma16816(float* c, const uint32_t* a,
                                                const uint32_t* b) {
    asm volatile("mma.sync.aligned.m16n8k16.row.col.f32.f16.f16.f32 "
                 "{%0,%1,%2,%3}, {%4,%5,%6,%7}, {%8,%9}, {%0,%1,%2,%3};"
                 : "+f"(c[0]), "+f"(c[1]), "+f"(c[2]), "+f"(c[3])
                 : "r"(a[0]), "r"(a[1]), "r"(a[2]), "r"(a[3]), "r"(b[0]), "r"(b[1]));
}
static __device__ __forceinline__ void cpa16(uint32_t dst, const void* src) {
    asm volatile("cp.async.cg.shared.global [%0], [%1], 16;" :: "r"(dst), "l"(src) : "memory");
}
#define CPA_COMMIT() asm volatile("cp.async.commit_group;" ::: "memory")
#define CPA_WAIT(n)  asm volatile("cp.async.wait_group %0;" :: "n"(n) : "memory")

// 128x128 fp16 tile -> smem, 256B rows, 16B-chunk xor swizzle (256 threads).
static __device__ __forceinline__ void cpa_tile(uint32_t dst_s,
                                                const __half* src,
                                                int row0, int tid) {
    const char* base = (const char*)(src + (size_t)row0 * D);
    #pragma unroll
    for (int i = 0; i < 8; i++) {
        int idx = tid + i * 256;
        int r = idx >> 4, c = idx & 15;
        uint32_t off = (uint32_t)r * 256 + (uint32_t)((c ^ (r & 7)) << 4);
        cpa16(dst_s + off, base + (size_t)r * 256 + c * 16);
    }
}

// ---------------------------------------------------------------------------
// Prep v2: 16 rows/block, 256 threads. Thread (r=tid>>4, c=tid&15):
// conversion+sqnorm via 16-lane groups, dc via serial 128-FMA dot per (row,center).
#define XS_STRIDE 136   // floats; 136%32=8 banks apart per row, float4-aligned
__global__ void k_split(const float* __restrict__ X, const float* __restrict__ C) {
    __shared__ float cn4[32 * 16 * 4];     // [k4][c][4] -> 8KB
    __shared__ float xs[16 * XS_STRIDE];   // padded rows
    __shared__ float srow[16];
    const int tid = threadIdx.x, wid = tid >> 5, lane = tid & 31;
    const int r = tid >> 4, c = tid & 15;

    // Normalize centers into cn4 (warp w handles centers w, w+8).
    #pragma unroll
    for (int cc = wid; cc < P; cc += 8) {
        float4 v = ((const float4*)(C + (size_t)cc * D))[lane];
        float s = v.x * v.x + v.y * v.y + v.z * v.z + v.w * v.w;
        #pragma unroll
        for (int o = 16; o; o >>= 1) s += __shfl_xor_sync(0xffffffffu, s, o);
        float inv = 1.0f / sqrtf(s);
        float* dst = &cn4[lane * 64 + cc * 4];
        dst[0] = v.x * inv; dst[1] = v.y * inv; dst[2] = v.z * inv; dst[3] = v.w * inv;
    }

    // Row conversion + sqnorm: thread handles 8 elems of its row.
    const int row = blockIdx.x * 16 + r;
    float4 v0 = ((const float4*)X)[(size_t)row * 32 + c * 2];
    float4 v1 = ((const float4*)X)[(size_t)row * 32 + c * 2 + 1];
    {
        __half2 p0 = __halves2half2(__float2half(v0.x), __float2half(v0.y));
        __half2 p1 = __halves2half2(__float2half(v0.z), __float2half(v0.w));
        __half2 p2 = __halves2half2(__float2half(v1.x), __float2half(v1.y));
        __half2 p3 = __halves2half2(__float2half(v1.z), __float2half(v1.w));
        uint4 pk;
        pk.x = *(uint32_t*)&p0; pk.y = *(uint32_t*)&p1;
        pk.z = *(uint32_t*)&p2; pk.w = *(uint32_t*)&p3;
        ((uint4*)g_xh)[(size_t)row * 16 + c] = pk;
    }
    float sp = v0.x * v0.x + v0.y * v0.y + v0.z * v0.z + v0.w * v0.w
             + v1.x * v1.x + v1.y * v1.y + v1.z * v1.z + v1.w * v1.w;
    #pragma unroll
    for (int o = 8; o; o >>= 1) sp += __shfl_xor_sync(0xffffffffu, sp, o);
    *(float4*)&xs[r * XS_STRIDE + c * 8]     = v0;
    *(float4*)&xs[r * XS_STRIDE + c * 8 + 4] = v1;
    if (c == 0) srow[r] = sp;
    __syncthreads();

    // dc: thread (r, c) computes dist(row r, center c), then min over 16.
    float dot = 0.0f;
    #pragma unroll 8
    for (int k4 = 0; k4 < 32; k4++) {
        float4 xv = *(const float4*)&xs[r * XS_STRIDE + k4 * 4];
        float4 cv = *(const float4*)&cn4[k4 * 64 + c * 4];
        dot = fmaf(xv.x, cv.x, dot); dot = fmaf(xv.y, cv.y, dot);
        dot = fmaf(xv.z, cv.z, dot); dot = fmaf(xv.w, cv.w, dot);
    }
    float s = srow[r];
    float d2 = fmaf(-2.0f, dot, s + 1.0f);
    float dcv = fmaxf(sqrtf(fmaxf(d2, 0.0f)), EPSF);
    #pragma unroll
    for (int o = 8; o; o >>= 1) dcv = fminf(dcv, __shfl_xor_sync(0xffffffffu, dcv, o));
    if (c == 0) { g_sq[row] = s; g_maxp[row] = 0; g_minn[row] = INFBITS; g_dc[row] = dcv; }
}

// ---------------------------------------------------------------------------
// Persistent symmetric mining: 2112 (I,k) tiles split evenly over 148 blocks.
// 256 threads, 8 warps: warp (wid&3)->32-row M block, (wid>>2)->64-col N half.
// Pure fp16 1-pass; warp tile 32x64 (better ldsm:mma ratio).
__global__ void __launch_bounds__(256, 1)
k_main(const int* __restrict__ T) {
    extern __shared__ __align__(1024) char smem[];
    __shared__ int   tCol[2][BN];
    __shared__ float sqCol[2][BN];

    const int tid  = threadIdx.x;
    const int lane = tid & 31;
    const int wid  = tid >> 5;
    const int mw   = wid & 3;
    const int nh   = wid >> 2;
    const int wm0  = mw * 32;
    const int wn0  = nh * 64;
    const uint32_t sb = smem_u32(smem);

    const int beg = (blockIdx.x * TOT) / GRIDX;
    const int end = ((blockIdx.x + 1) * TOT) / GRIDX;

    uint32_t a_rowoff[2], b_coloff[4];
    const uint32_t a_chk = (uint32_t)(lane >> 4);
    const uint32_t b_chk = (uint32_t)((lane >> 3) & 1);
    #pragma unroll
    for (int i = 0; i < 2; i++) {
        uint32_t r = wm0 + i * 16 + (lane & 7) + ((lane >> 3) & 1) * 8;
        a_rowoff[i] = (r * 256) | ((r & 7) << 28);
    }
    #pragma unroll
    for (int jj = 0; jj < 4; jj++) {
        uint32_t cc = wn0 + jj * 16 + (lane & 7) + (lane >> 4) * 8;
        b_coloff[jj] = (cc * 256) | ((cc & 7) << 28);
    }

    int curI = beg / NK;
    float sqr[2][2]; int trow[2][2];
    #pragma unroll
    for (int i = 0; i < 2; i++)
        #pragma unroll
        for (int h = 0; h < 2; h++) {
            int gr = curI * BM + wm0 + i * 16 + h * 8 + (lane >> 2);
            sqr[i][h] = g_sq[gr];
            trow[i][h] = T[gr];
        }

    // Prologue: A(curI) + B(first J) + labels into buf 0.
    cpa_tile(sb + SMA, g_xh, curI * BM, tid);
    {
        int J0 = (curI + (beg - curI * NK)) & (NB - 1);
        cpa_tile(sb + SMB0, g_xh, J0 * BN, tid);
        if (tid < BN) { tCol[0][tid] = T[J0 * BN + tid]; sqCol[0][tid] = g_sq[J0 * BN + tid]; }
    }
    CPA_COMMIT();

    float mp[2][2], mn[2][2];
    #pragma unroll
    for (int i = 0; i < 2; i++)
        #pragma unroll
        for (int h = 0; h < 2; h++) { mp[i][h] = -1.0f; mn[i][h] = FINF; }

    for (int idx = beg; idx < end; idx++) {
        const int I = idx / NK;
        const int J = (I + (idx - I * NK)) & (NB - 1);
        const uint32_t buf = (uint32_t)((idx - beg) & 1);

        CPA_WAIT(0);
        __syncthreads();        // B(idx) resident; all warps done with prev iter

        if (I != curI) {
            // Flush row stats for curI.
            #pragma unroll
            for (int i = 0; i < 2; i++)
                #pragma unroll
                for (int h = 0; h < 2; h++) {
                    float p = mp[i][h], q = mn[i][h];
                    #pragma unroll
                    for (int o = 1; o <= 2; o <<= 1) {
                        p = fmaxf(p, __shfl_xor_sync(0xffffffffu, p, o));
                        q = fminf(q, __shfl_xor_sync(0xffffffffu, q, o));
                    }
                    if ((lane & 3) == 0) {
                        int gr = curI * BM + wm0 + i * 16 + h * 8 + (lane >> 2);
                        atomicMax(&g_maxp[gr], __float_as_int(p));
                        atomicMin(&g_minn[gr], __float_as_int(q));
                    }
                    mp[i][h] = -1.0f; mn[i][h] = FINF;
                }
            curI = I;
            #pragma unroll
            for (int i = 0; i < 2; i++)
                #pragma unroll
                for (int h = 0; h < 2; h++) {
                    int gr = curI * BM + wm0 + i * 16 + h * 8 + (lane >> 2);
                    sqr[i][h] = g_sq[gr];
                    trow[i][h] = T[gr];
                }
            // Reload A (safe: all warps passed the sync above).
            cpa_tile(sb + SMA, g_xh, curI * BM, tid);
            CPA_COMMIT();
            if (idx + 1 < end) {
                int I1 = (idx + 1) / NK;
                int J1 = (I1 + (idx + 1 - I1 * NK)) & (NB - 1);
                cpa_tile(sb + SMB0 + (buf ^ 1) * SMB_SZ, g_xh, J1 * BN, tid);
                CPA_COMMIT();
                if (tid < BN) {
                    tCol[buf ^ 1][tid] = T[J1 * BN + tid];
                    sqCol[buf ^ 1][tid] = g_sq[J1 * BN + tid];
                }
                CPA_WAIT(1);    // A resident, B(idx+1) may still fly
            } else {
                CPA_WAIT(0);
            }
            __syncthreads();
        } else if (idx + 1 < end) {
            int I1 = (idx + 1) / NK;
            int J1 = (I1 + (idx + 1 - I1 * NK)) & (NB - 1);
            cpa_tile(sb + SMB0 + (buf ^ 1) * SMB_SZ, g_xh, J1 * BN, tid);
            CPA_COMMIT();
            if (tid < BN) {
                tCol[buf ^ 1][tid] = T[J1 * BN + tid];
                sqCol[buf ^ 1][tid] = g_sq[J1 * BN + tid];
            }
        }

        float acc[2][8][4];
        #pragma unroll
        for (int i = 0; i < 2; i++)
            #pragma unroll
            for (int j = 0; j < 8; j++)
                #pragma unroll
                for (int e = 0; e < 4; e++) acc[i][j][e] = 0.0f;

        const uint32_t ab = sb + SMA;
        const uint32_t bb = sb + SMB0 + buf * SMB_SZ;

        #pragma unroll
        for (int ks = 0; ks < 8; ks++) {
            uint32_t a_f[2][4], b_f[4][4];
            const uint32_t achunk = (uint32_t)(2 * ks) + a_chk;
            const uint32_t bchunk = (uint32_t)(2 * ks) + b_chk;
            #pragma unroll
            for (int i = 0; i < 2; i++) {
                uint32_t ro = a_rowoff[i];
                uint32_t off = (ro & 0x0FFFFFFFu) + ((achunk ^ (ro >> 28)) << 4);
                ldsm4(a_f[i], ab + off);
            }
            #pragma unroll
            for (int jj = 0; jj < 4; jj++) {
                uint32_t co = b_coloff[jj];
                uint32_t off = (co & 0x0FFFFFFFu) + ((bchunk ^ (co >> 28)) << 4);
                ldsm4(b_f[jj], bb + off);
            }
            #pragma unroll
            for (int i = 0; i < 2; i++)
                #pragma unroll
                for (int jj = 0; jj < 4; jj++) {
                    mma16816(acc[i][2 * jj],     a_f[i], &b_f[jj][0]);
                    mma16816(acc[i][2 * jj + 1], a_f[i], &b_f[jj][2]);
                }
        }

        // Fused mining: row stats (registers) + col stats -> atomics.
        #pragma unroll
        for (int j = 0; j < 8; j++) {
            int cb = wn0 + j * 8 + (lane & 3) * 2;
            int tc0 = tCol[buf][cb], tc1 = tCol[buf][cb + 1];
            float sc0 = sqCol[buf][cb], sc1 = sqCol[buf][cb + 1];
            float cmax0 = -1.0f, cmax1 = -1.0f, cmin0 = FINF, cmin1 = FINF;
            #pragma unroll
            for (int i = 0; i < 2; i++)
                #pragma unroll
                for (int h = 0; h < 2; h++) {
                    float d0 = fmaxf(fmaf(-2.0f, acc[i][j][2 * h],     sqr[i][h] + sc0), 0.0f);
                    float d1 = fmaxf(fmaf(-2.0f, acc[i][j][2 * h + 1], sqr[i][h] + sc1), 0.0f);
                    if (trow[i][h] == tc0) { mp[i][h] = fmaxf(mp[i][h], d0);
                                             cmax0 = fmaxf(cmax0, d0); }
                    else                   { mn[i][h] = fminf(mn[i][h], d0);
                                             cmin0 = fminf(cmin0, d0); }
                    if (trow[i][h] == tc1) { mp[i][h] = fmaxf(mp[i][h], d1);
                                             cmax1 = fmaxf(cmax1, d1); }
                    else                   { mn[i][h] = fminf(mn[i][h], d1);
                                             cmin1 = fminf(cmin1, d1); }
                }
            #pragma unroll
            for (int o = 4; o <= 16; o <<= 1) {
                cmax0 = fmaxf(cmax0, __shfl_xor_sync(0xffffffffu, cmax0, o));
                cmin0 = fminf(cmin0, __shfl_xor_sync(0xffffffffu, cmin0, o));
                cmax1 = fmaxf(cmax1, __shfl_xor_sync(0xffffffffu, cmax1, o));
                cmin1 = fminf(cmin1, __shfl_xor_sync(0xffffffffu, cmin1, o));
            }
            if (lane < 4) {
                int gcol = J * BN + wn0 + j * 8 + lane * 2;
                atomicMax(&g_maxp[gcol], __float_as_int(cmax0));
                atomicMin(&g_minn[gcol], __float_as_int(cmin0));
                atomicMax(&g_maxp[gcol + 1], __float_as_int(cmax1));
                atomicMin(&g_minn[gcol + 1], __float_as_int(cmin1));
            }
        }
    }

    // Final row-stat flush for the last I.
    #pragma unroll
    for (int i = 0; i < 2; i++)
        #pragma unroll
        for (int h = 0; h < 2; h++) {
            float p = mp[i][h], q = mn[i][h];
            #pragma unroll
            for (int o = 1; o <= 2; o <<= 1) {
                p = fmaxf(p, __shfl_xor_sync(0xffffffffu, p, o));
                q = fminf(q, __shfl_xor_sync(0xffffffffu, q, o));
            }
            if ((lane & 3) == 0) {
                int gr = curI * BM + wm0 + i * 16 + h * 8 + (lane >> 2);
                atomicMax(&g_maxp[gr], __float_as_int(p));
                atomicMin(&g_minn[gr], __float_as_int(q));
            }
        }
}

// ---------------------------------------------------------------------------
// Final loss: one block, deterministic fixed-order accumulation + tree sum.
__global__ void k_loss(float* __restrict__ out) {
    __shared__ float sh[1024];
    const int t = threadIdx.x;
    float sum = 0.0f;
    #pragma unroll
    for (int k = 0; k < N / 1024; k++) {
        int r = t + k * 1024;
        float mpv = __int_as_float(g_maxp[r]);
        float mnv = __int_as_float(g_minn[r]);
        float dap = sqrtf(fmaxf(mpv, EPSF));
        float dan = isinf(mnv) ? (dap + MARGINF) : sqrtf(fmaxf(mnv, EPSF));
        dan = fminf(dan, g_dc[r]);
        sum += fmaxf(dap - dan + MARGINF, 0.0f);
    }
    sh[t] = sum;
    __syncthreads();
    for (int s = 512; s; s >>= 1) {
        if (t < s) sh[t] += sh[t + s];
        __syncthreads();
    }
    if (t == 0) out[0] = sh[0] / (float)N;
}

// ---------------------------------------------------------------------------
extern "C" void kernel_launch(void* const* d_in, const int* in_sizes, int n_in,
                              void* d_out, int out_size) {
    const float* X = (const float*)d_in[0];
    const int*   T = (const int*)d_in[1];
    const float* C = (const float*)d_in[2];
    float* out = (float*)d_out;

    cudaFuncSetAttribute(k_main, cudaFuncAttributeMaxDynamicSharedMemorySize, SMEM_TOTAL);

    k_split<<<N / 16, 256>>>(X, C);
    k_main<<<GRIDX, 256, SMEM_TOTAL>>>(T);
    k_loss<<<1, 1024>>>(out);
}

// round 16
// speedup vs baseline: 1.9535x; 1.0977x over previous
#include <cuda_runtime.h>
#include <cuda_fp16.h>
#include <cstdint>

#define N       8192
#define D       128
#define BM      128
#define BN      128
#define NB      64
#define NK      33          // offsets 0..32 cover all pairs (circulant)
#define TOT     (NB * NK)   // 2112 tiles
#define GRIDX   296         // 2 persistent CTAs per SM
#define P       16
#define MARGINF 1.0f
#define EPSF    1e-12f
#define FINF    __int_as_float(0x7f800000)
#define INFBITS 0x7f800000

// smem layout (dynamic, 96KB): A | B buf0 | B buf1
#define SMA     0u
#define SMB0    32768u
#define SMB_SZ  32768u
#define SMEM_TOTAL 98304

// Scratch (no allocation allowed -> device globals)
__device__ float g_sq[N];
__device__ int   g_maxp[N];     // float bits, order-independent atomics
__device__ int   g_minn[N];
__device__ float g_dc[N];       // min distance to normalized centers
__device__ __half g_xh[N * D];

// ---------------------------------------------------------------------------
static __device__ __forceinline__ uint32_t smem_u32(const void* p) {
    uint32_t a;
    asm("{ .reg .u64 t; cvta.to.shared.u64 t, %1; cvt.u32.u64 %0, t; }" : "=r"(a) : "l"(p));
    return a;
}
static __device__ __forceinline__ void ldsm4(uint32_t* r, uint32_t addr) {
    asm volatile("ldmatrix.sync.aligned.m8n8.x4.shared.b16 {%0,%1,%2,%3}, [%4];"
                 : "=r"(r[0]), "=r"(r[1]), "=r"(r[2]), "=r"(r[3]) : "r"(addr));
}
static __device__ __forceinline__ void mma16816(float* c, const uint32_t* a,
                                                const uint32_t* b) {
    asm volatile("mma.sync.aligned.m16n8k16.row.col.f32.f16.f16.f32 "
                 "{%0,%1,%2,%3}, {%4,%5,%6,%7}, {%8,%9}, {%0,%1,%2,%3};"
                 : "+f"(c[0]), "+f"(c[1]), "+f"(c[2]), "+f"(c[3])
                 : "r"(a[0]), "r"(a[1]), "r"(a[2]), "r"(a[3]), "r"(b[0]), "r"(b[1]));
}
static __device__ __forceinline__ void cpa16(uint32_t dst, const void* src) {
    asm volatile("cp.async.cg.shared.global [%0], [%1], 16;" :: "r"(dst), "l"(src) : "memory");
}
#define CPA_COMMIT() asm volatile("cp.async.commit_group;" ::: "memory")
#define CPA_WAIT(n)  asm volatile("cp.async.wait_group %0;" :: "n"(n) : "memory")

// 128x128 fp16 tile -> smem, 256B rows, 16B-chunk xor swizzle (256 threads).
static __device__ __forceinline__ void cpa_tile(uint32_t dst_s,
                                                const __half* src,
                                                int row0, int tid) {
    const char* base = (const char*)(src + (size_t)row0 * D);
    #pragma unroll
    for (int i = 0; i < 8; i++) {
        int idx = tid + i * 256;
        int r = idx >> 4, c = idx & 15;
        uint32_t off = (uint32_t)r * 256 + (uint32_t)((c ^ (r & 7)) << 4);
        cpa16(dst_s + off, base + (size_t)r * 256 + c * 16);
    }
}

// ---------------------------------------------------------------------------
// Prep: 16 rows/block, 256 threads. Thread (r=tid>>4, c=tid&15):
// conversion+sqnorm via 16-lane groups, dc via 2-chain 128-FMA dot per (row,center).
#define XS_STRIDE 136   // floats; float4-aligned, bank-staggered rows
__global__ void k_split(const float* __restrict__ X, const float* __restrict__ C) {
    __shared__ float cn4[32 * 16 * 4];     // [k4][c][4] -> 8KB
    __shared__ float xs[16 * XS_STRIDE];   // padded rows
    __shared__ float srow[16];
    const int tid = threadIdx.x, wid = tid >> 5, lane = tid & 31;
    const int r = tid >> 4, c = tid & 15;

    // Normalize centers into cn4 (warp w handles centers w, w+8).
    #pragma unroll
    for (int cc = wid; cc < P; cc += 8) {
        float4 v = ((const float4*)(C + (size_t)cc * D))[lane];
        float s = v.x * v.x + v.y * v.y + v.z * v.z + v.w * v.w;
        #pragma unroll
        for (int o = 16; o; o >>= 1) s += __shfl_xor_sync(0xffffffffu, s, o);
        float inv = 1.0f / sqrtf(s);
        float* dst = &cn4[lane * 64 + cc * 4];
        dst[0] = v.x * inv; dst[1] = v.y * inv; dst[2] = v.z * inv; dst[3] = v.w * inv;
    }

    // Row conversion + sqnorm: thread handles 8 elems of its row.
    const int row = blockIdx.x * 16 + r;
    float4 v0 = ((const float4*)X)[(size_t)row * 32 + c * 2];
    float4 v1 = ((const float4*)X)[(size_t)row * 32 + c * 2 + 1];
    {
        __half2 p0 = __halves2half2(__float2half(v0.x), __float2half(v0.y));
        __half2 p1 = __halves2half2(__float2half(v0.z), __float2half(v0.w));
        __half2 p2 = __halves2half2(__float2half(v1.x), __float2half(v1.y));
        __half2 p3 = __halves2half2(__float2half(v1.z), __float2half(v1.w));
        uint4 pk;
        pk.x = *(uint32_t*)&p0; pk.y = *(uint32_t*)&p1;
        pk.z = *(uint32_t*)&p2; pk.w = *(uint32_t*)&p3;
        ((uint4*)g_xh)[(size_t)row * 16 + c] = pk;
    }
    float sp = v0.x * v0.x + v0.y * v0.y + v0.z * v0.z + v0.w * v0.w
             + v1.x * v1.x + v1.y * v1.y + v1.z * v1.z + v1.w * v1.w;
    #pragma unroll
    for (int o = 8; o; o >>= 1) sp += __shfl_xor_sync(0xffffffffu, sp, o);
    *(float4*)&xs[r * XS_STRIDE + c * 8]     = v0;
    *(float4*)&xs[r * XS_STRIDE + c * 8 + 4] = v1;
    if (c == 0) srow[r] = sp;
    __syncthreads();

    // dc: thread (r, c) computes dist(row r, center c); two chains for ILP.
    float dotA = 0.0f, dotB = 0.0f;
    #pragma unroll 8
    for (int k4 = 0; k4 < 32; k4 += 2) {
        float4 x0 = *(const float4*)&xs[r * XS_STRIDE + k4 * 4];
        float4 c0 = *(const float4*)&cn4[k4 * 64 + c * 4];
        float4 x1 = *(const float4*)&xs[r * XS_STRIDE + (k4 + 1) * 4];
        float4 c1 = *(const float4*)&cn4[(k4 + 1) * 64 + c * 4];
        dotA = fmaf(x0.x, c0.x, dotA); dotA = fmaf(x0.y, c0.y, dotA);
        dotA = fmaf(x0.z, c0.z, dotA); dotA = fmaf(x0.w, c0.w, dotA);
        dotB = fmaf(x1.x, c1.x, dotB); dotB = fmaf(x1.y, c1.y, dotB);
        dotB = fmaf(x1.z, c1.z, dotB); dotB = fmaf(x1.w, c1.w, dotB);
    }
    float dot = dotA + dotB;
    float s = srow[r];
    float d2 = fmaf(-2.0f, dot, s + 1.0f);
    float dcv = fmaxf(sqrtf(fmaxf(d2, 0.0f)), EPSF);
    #pragma unroll
    for (int o = 8; o; o >>= 1) dcv = fminf(dcv, __shfl_xor_sync(0xffffffffu, dcv, o));
    if (c == 0) { g_sq[row] = s; g_maxp[row] = 0; g_minn[row] = INFBITS; g_dc[row] = dcv; }
}

// ---------------------------------------------------------------------------
// Persistent symmetric mining: 2112 (I,k) tiles split evenly over 296 blocks
// (2 CTAs/SM -> cross-CTA phase overlap). 256 threads, warp tile 32x64, fp16.
__global__ void __launch_bounds__(256, 2)
k_main(const int* __restrict__ T) {
    extern __shared__ __align__(1024) char smem[];
    __shared__ int   tCol[2][BN];
    __shared__ float sqCol[2][BN];

    const int tid  = threadIdx.x;
    const int lane = tid & 31;
    const int wid  = tid >> 5;
    const int mw   = wid & 3;
    const int nh   = wid >> 2;
    const int wm0  = mw * 32;
    const int wn0  = nh * 64;
    const uint32_t sb = smem_u32(smem);

    const int beg = (blockIdx.x * TOT) / GRIDX;
    const int end = ((blockIdx.x + 1) * TOT) / GRIDX;

    uint32_t a_rowoff[2], b_coloff[4];
    const uint32_t a_chk = (uint32_t)(lane >> 4);
    const uint32_t b_chk = (uint32_t)((lane >> 3) & 1);
    #pragma unroll
    for (int i = 0; i < 2; i++) {
        uint32_t r = wm0 + i * 16 + (lane & 7) + ((lane >> 3) & 1) * 8;
        a_rowoff[i] = (r * 256) | ((r & 7) << 28);
    }
    #pragma unroll
    for (int jj = 0; jj < 4; jj++) {
        uint32_t cc = wn0 + jj * 16 + (lane & 7) + (lane >> 4) * 8;
        b_coloff[jj] = (cc * 256) | ((cc & 7) << 28);
    }

    int curI = beg / NK;
    float sqr[2][2]; int trow[2][2];
    #pragma unroll
    for (int i = 0; i < 2; i++)
        #pragma unroll
        for (int h = 0; h < 2; h++) {
            int gr = curI * BM + wm0 + i * 16 + h * 8 + (lane >> 2);
            sqr[i][h] = g_sq[gr];
            trow[i][h] = T[gr];
        }

    // Prologue: A(curI) + B(first J) + labels into buf 0.
    cpa_tile(sb + SMA, g_xh, curI * BM, tid);
    {
        int J0 = (curI + (beg - curI * NK)) & (NB - 1);
        cpa_tile(sb + SMB0, g_xh, J0 * BN, tid);
        if (tid < BN) { tCol[0][tid] = T[J0 * BN + tid]; sqCol[0][tid] = g_sq[J0 * BN + tid]; }
    }
    CPA_COMMIT();

    float mp[2][2], mn[2][2];
    #pragma unroll
    for (int i = 0; i < 2; i++)
        #pragma unroll
        for (int h = 0; h < 2; h++) { mp[i][h] = -1.0f; mn[i][h] = FINF; }

    for (int idx = beg; idx < end; idx++) {
        const int I = idx / NK;
        const int J = (I + (idx - I * NK)) & (NB - 1);
        const uint32_t buf = (uint32_t)((idx - beg) & 1);

        CPA_WAIT(0);
        __syncthreads();        // B(idx) resident; all warps done with prev iter

        if (I != curI) {
            // Flush row stats for curI.
            #pragma unroll
            for (int i = 0; i < 2; i++)
                #pragma unroll
                for (int h = 0; h < 2; h++) {
                    float p = mp[i][h], q = mn[i][h];
                    #pragma unroll
                    for (int o = 1; o <= 2; o <<= 1) {
                        p = fmaxf(p, __shfl_xor_sync(0xffffffffu, p, o));
                        q = fminf(q, __shfl_xor_sync(0xffffffffu, q, o));
                    }
                    if ((lane & 3) == 0) {
                        int gr = curI * BM + wm0 + i * 16 + h * 8 + (lane >> 2);
                        atomicMax(&g_maxp[gr], __float_as_int(p));
                        atomicMin(&g_minn[gr], __float_as_int(q));
                    }
                    mp[i][h] = -1.0f; mn[i][h] = FINF;
                }
            curI = I;
            #pragma unroll
            for (int i = 0; i < 2; i++)
                #pragma unroll
                for (int h = 0; h < 2; h++) {
                    int gr = curI * BM + wm0 + i * 16 + h * 8 + (lane >> 2);
                    sqr[i][h] = g_sq[gr];
                    trow[i][h] = T[gr];
                }
            // Reload A (safe: all warps passed the sync above).
            cpa_tile(sb + SMA, g_xh, curI * BM, tid);
            CPA_COMMIT();
            if (idx + 1 < end) {
                int I1 = (idx + 1) / NK;
                int J1 = (I1 + (idx + 1 - I1 * NK)) & (NB - 1);
                cpa_tile(sb + SMB0 + (buf ^ 1) * SMB_SZ, g_xh, J1 * BN, tid);
                CPA_COMMIT();
                if (tid < BN) {
                    tCol[buf ^ 1][tid] = T[J1 * BN + tid];
                    sqCol[buf ^ 1][tid] = g_sq[J1 * BN + tid];
                }
                CPA_WAIT(1);    // A resident, B(idx+1) may still fly
            } else {
                CPA_WAIT(0);
            }
            __syncthreads();
        } else if (idx + 1 < end) {
            int I1 = (idx + 1) / NK;
            int J1 = (I1 + (idx + 1 - I1 * NK)) & (NB - 1);
            cpa_tile(sb + SMB0 + (buf ^ 1) * SMB_SZ, g_xh, J1 * BN, tid);
            CPA_COMMIT();
            if (tid < BN) {
                tCol[buf ^ 1][tid] = T[J1 * BN + tid];
                sqCol[buf ^ 1][tid] = g_sq[J1 * BN + tid];
            }
        }

        float acc[2][8][4];
        #pragma unroll
        for (int i = 0; i < 2; i++)
            #pragma unroll
            for (int j = 0; j < 8; j++)
                #pragma unroll
                for (int e = 0; e < 4; e++) acc[i][j][e] = 0.0f;

        const uint32_t ab = sb + SMA;
        const uint32_t bb = sb + SMB0 + buf * SMB_SZ;

        #pragma unroll
        for (int ks = 0; ks < 8; ks++) {
            uint32_t a_f[2][4], b_f[4][4];
            const uint32_t achunk = (uint32_t)(2 * ks) + a_chk;
            const uint32_t bchunk = (uint32_t)(2 * ks) + b_chk;
            #pragma unroll
            for (int i = 0; i < 2; i++) {
                uint32_t ro = a_rowoff[i];
                uint32_t off = (ro & 0x0FFFFFFFu) + ((achunk ^ (ro >> 28)) << 4);
                ldsm4(a_f[i], ab + off);
            }
            #pragma unroll
            for (int jj = 0; jj < 4; jj++) {
                uint32_t co = b_coloff[jj];
                uint32_t off = (co & 0x0FFFFFFFu) + ((bchunk ^ (co >> 28)) << 4);
                ldsm4(b_f[jj], bb + off);
            }
            #pragma unroll
            for (int i = 0; i < 2; i++)
                #pragma unroll
                for (int jj = 0; jj < 4; jj++) {
                    mma16816(acc[i][2 * jj],     a_f[i], &b_f[jj][0]);
                    mma16816(acc[i][2 * jj + 1], a_f[i], &b_f[jj][2]);
                }
        }

        // Fused mining: row stats (registers) + col stats -> atomics.
        #pragma unroll
        for (int j = 0; j < 8; j++) {
            int cb = wn0 + j * 8 + (lane & 3) * 2;
            int tc0 = tCol[buf][cb], tc1 = tCol[buf][cb + 1];
            float sc0 = sqCol[buf][cb], sc1 = sqCol[buf][cb + 1];
            float cmax0 = -1.0f, cmax1 = -1.0f, cmin0 = FINF, cmin1 = FINF;
            #pragma unroll
            for (int i = 0; i < 2; i++)
                #pragma unroll
                for (int h = 0; h < 2; h++) {
                    float d0 = fmaxf(fmaf(-2.0f, acc[i][j][2 * h],     sqr[i][h] + sc0), 0.0f);
                    float d1 = fmaxf(fmaf(-2.0f, acc[i][j][2 * h + 1], sqr[i][h] + sc1), 0.0f);
                    if (trow[i][h] == tc0) { mp[i][h] = fmaxf(mp[i][h], d0);
                                             cmax0 = fmaxf(cmax0, d0); }
                    else                   { mn[i][h] = fminf(mn[i][h], d0);
                                             cmin0 = fminf(cmin0, d0); }
                    if (trow[i][h] == tc1) { mp[i][h] = fmaxf(mp[i][h], d1);
                                             cmax1 = fmaxf(cmax1, d1); }
                    else                   { mn[i][h] = fminf(mn[i][h], d1);
                                             cmin1 = fminf(cmin1, d1); }
                }
            #pragma unroll
            for (int o = 4; o <= 16; o <<= 1) {
                cmax0 = fmaxf(cmax0, __shfl_xor_sync(0xffffffffu, cmax0, o));
                cmin0 = fminf(cmin0, __shfl_xor_sync(0xffffffffu, cmin0, o));
                cmax1 = fmaxf(cmax1, __shfl_xor_sync(0xffffffffu, cmax1, o));
                cmin1 = fminf(cmin1, __shfl_xor_sync(0xffffffffu, cmin1, o));
            }
            if (lane < 4) {
                int gcol = J * BN + wn0 + j * 8 + lane * 2;
                atomicMax(&g_maxp[gcol], __float_as_int(cmax0));
                atomicMin(&g_minn[gcol], __float_as_int(cmin0));
                atomicMax(&g_maxp[gcol + 1], __float_as_int(cmax1));
                atomicMin(&g_minn[gcol + 1], __float_as_int(cmin1));
            }
        }
    }

    // Final row-stat flush for the last I.
    #pragma unroll
    for (int i = 0; i < 2; i++)
        #pragma unroll
        for (int h = 0; h < 2; h++) {
            float p = mp[i][h], q = mn[i][h];
            #pragma unroll
            for (int o = 1; o <= 2; o <<= 1) {
                p = fmaxf(p, __shfl_xor_sync(0xffffffffu, p, o));
                q = fminf(q, __shfl_xor_sync(0xffffffffu, q, o));
            }
            if ((lane & 3) == 0) {
                int gr = curI * BM + wm0 + i * 16 + h * 8 + (lane >> 2);
                atomicMax(&g_maxp[gr], __float_as_int(p));
                atomicMin(&g_minn[gr], __float_as_int(q));
            }
        }
}

// ---------------------------------------------------------------------------
// Final loss: one block, deterministic fixed-order accumulation + tree sum.
__global__ void k_loss(float* __restrict__ out) {
    __shared__ float sh[1024];
    const int t = threadIdx.x;
    float sum = 0.0f;
    #pragma unroll
    for (int k = 0; k < N / 1024; k++) {
        int r = t + k * 1024;
        float mpv = __int_as_float(g_maxp[r]);
        float mnv = __int_as_float(g_minn[r]);
        float dap = sqrtf(fmaxf(mpv, EPSF));
        float dan = isinf(mnv) ? (dap + MARGINF) : sqrtf(fmaxf(mnv, EPSF));
        dan = fminf(dan, g_dc[r]);
        sum += fmaxf(dap - dan + MARGINF, 0.0f);
    }
    sh[t] = sum;
    __syncthreads();
    for (int s = 512; s; s >>= 1) {
        if (t < s) sh[t] += sh[t + s];
        __syncthreads();
    }
    if (t == 0) out[0] = sh[0] / (float)N;
}

// ---------------------------------------------------------------------------
extern "C" void kernel_launch(void* const* d_in, const int* in_sizes, int n_in,
                              void* d_out, int out_size) {
    const float* X = (const float*)d_in[0];
    const int*   T = (const int*)d_in[1];
    const float* C = (const float*)d_in[2];
    float* out = (float*)d_out;

    cudaFuncSetAttribute(k_main, cudaFuncAttributeMaxDynamicSharedMemorySize, SMEM_TOTAL);

    k_split<<<N / 16, 256>>>(X, C);
    k_main<<<GRIDX, 256, SMEM_TOTAL>>>(T);
    k_loss<<<1, 1024>>>(out);
}